// round 2
// baseline (speedup 1.0000x reference)
#include <cuda_runtime.h>

#define N_NODES_MAX 50000
#define FEAT 300
#define HID 256

// ---------------- device scratch (no allocations allowed) ----------------
__device__ __align__(16) float g_deg [N_NODES_MAX];
__device__ __align__(16) float g_dis [N_NODES_MAX];
__device__ __align__(16) float g_dinv[N_NODES_MAX];
__device__ __align__(16) float g_z   [N_NODES_MAX * FEAT];   // dis[src]-scaled features
__device__ __align__(16) float g_agg [N_NODES_MAX * FEAT];   // edge-aggregated features
__device__ __align__(16) float g_sf  [N_NODES_MAX * 2 * HID];// per node: [0:256]=s, [256:512]=f
__device__ __align__(16) float g_u   [8 * 256];              // folded V-proj vectors per head
__device__ __align__(16) float g_c   [8];                    // folded V-bias per head
__device__ float g_konst[1];                   // out_proj_b . out_w + out_b
__device__ float g_acc [1];                    // sum of per-node contributions

// ---------------- f32x2 helpers (Blackwell packed fp32 pipe) ----------------
__device__ __forceinline__ void fma2(unsigned long long &d,
                                     unsigned long long a,
                                     unsigned long long b) {
    asm("fma.rn.f32x2 %0, %1, %2, %0;" : "+l"(d) : "l"(a), "l"(b));
}
__device__ __forceinline__ unsigned long long dup2(float x) {
    unsigned long long r;
    asm("mov.b64 %0, {%1, %1};" : "=l"(r) : "f"(x));
    return r;
}
__device__ __forceinline__ float2 unpack2(unsigned long long v) {
    float2 r;
    asm("mov.b64 {%0, %1}, %2;" : "=f"(r.x), "=f"(r.y) : "l"(v));
    return r;
}

// ---------------- phase 0: zero scratch ----------------
__global__ void k_zero(int n) {
    int i = blockIdx.x * blockDim.x + threadIdx.x;
    int stride = gridDim.x * blockDim.x;
    int tot4 = (n * FEAT) / 4;
    float4 z4 = make_float4(0.f, 0.f, 0.f, 0.f);
    float4* a4 = reinterpret_cast<float4*>(g_agg);
    for (int j = i; j < tot4; j += stride) a4[j] = z4;
    for (int j = i; j < n; j += stride) g_deg[j] = 0.f;
    if (i == 0) g_acc[0] = 0.f;
}

// ---------------- phase 1: in-degree (edge_index is int32!) ----------------
__global__ void k_deg(const int* __restrict__ ei, int E) {
    int i = blockIdx.x * blockDim.x + threadIdx.x;
    if (i < E) atomicAdd(&g_deg[ei[E + i]], 1.0f);
}

// ---------------- phase 2: normalizers ----------------
__global__ void k_dis(int n) {
    int i = blockIdx.x * blockDim.x + threadIdx.x;
    if (i < n) {
        float d = 1.0f + g_deg[i];
        g_dis[i]  = rsqrtf(d);
        g_dinv[i] = 1.0f / d;
    }
}

// ---------------- phase 3: z = dis[n] * x[n] ----------------
__global__ void k_z(const float* __restrict__ x) {
    int nblk = blockIdx.x;
    float s = g_dis[nblk];
    int base = nblk * FEAT;
    for (int k = threadIdx.x; k < FEAT; k += blockDim.x)
        g_z[base + k] = s * x[base + k];
}

// ---------------- phase 4: edge aggregation (1 warp / edge) ----------------
__global__ void k_edge(const int* __restrict__ ei, int E) {
    int w = (blockIdx.x * blockDim.x + threadIdx.x) >> 5;
    int lane = threadIdx.x & 31;
    if (w >= E) return;
    int s = __ldg(&ei[w]);
    int d = __ldg(&ei[E + w]);
    const float4* zr = reinterpret_cast<const float4*>(g_z + (size_t)s * FEAT);
    float4* ar = reinterpret_cast<float4*>(g_agg + (size_t)d * FEAT);
    #pragma unroll
    for (int c = lane; c < FEAT / 4; c += 32) {
        float4 v = __ldg(&zr[c]);
        asm volatile("red.global.add.v4.f32 [%0], {%1,%2,%3,%4};"
                     :: "l"(ar + c), "f"(v.x), "f"(v.y), "f"(v.z), "f"(v.w)
                     : "memory");
    }
}

// ---------------- phase 5: fold out_proj/out_w into per-head vectors ----------------
__global__ void k_prep(const float* __restrict__ ipw, const float* __restrict__ ipb,
                       const float* __restrict__ opw, const float* __restrict__ opb,
                       const float* __restrict__ ow,  const float* __restrict__ ob) {
    __shared__ float vout[256];
    int t = threadIdx.x;  // 256 threads
    float acc = 0.f;
    for (int j = 0; j < 256; j++) acc += opw[j * 256 + t] * ow[j];
    vout[t] = acc;
    __syncthreads();
    #pragma unroll
    for (int h = 0; h < 8; h++) {
        float a = 0.f;
        #pragma unroll 8
        for (int d = 0; d < 32; d++)
            a += ipw[(512 + h * 32 + d) * 256 + t] * vout[h * 32 + d];
        g_u[h * 256 + t] = a;
    }
    if (t < 8) {
        float c = 0.f;
        for (int d = 0; d < 32; d++) c += ipb[512 + t * 32 + d] * vout[t * 32 + d];
        g_c[t] = c;
    }
    if (t == 0) {
        float c = 0.f;
        for (int j = 0; j < 256; j++) c += opb[j] * ow[j];
        g_konst[0] = c + ob[0];
    }
}

// ---------------- phase 6: GCN GEMM  s/f = relu(y @ W + b) ----------------
// grid.y = 0 -> s (K=100, W_s), grid.y = 1 -> f (K=200, W_f)
#define C_KC 25
__global__ __launch_bounds__(256) void k_gcn(
        const float* __restrict__ x,
        const float* __restrict__ Wsg, const float* __restrict__ bsg,
        const float* __restrict__ Wfg, const float* __restrict__ bfg, int n) {
    __shared__ __align__(16) float ys[C_KC][68];     // transposed y tile [k][node]
    __shared__ __align__(16) float Wt[C_KC][260];    // W tile [k][col]
    __shared__ float sdis[64], sdinv[64];

    int part = blockIdx.y;
    const float* W    = part ? Wfg : Wsg;
    const float* bias = part ? bfg : bsg;
    int K    = part ? 200 : 100;
    int koff = part ? 100 : 0;
    int n0  = blockIdx.x * 64;
    int tid = threadIdx.x;

    if (tid < 64) {
        int nn = n0 + tid;
        sdis[tid]  = (nn < n) ? g_dis[nn]  : 0.f;
        sdinv[tid] = (nn < n) ? g_dinv[nn] : 0.f;
    }
    __syncthreads();

    int tm0 = (tid >> 5) * 8;   // node row base (warp-uniform -> broadcast LDS)
    int tn0 = (tid & 31) * 8;   // col base

    unsigned long long acc[8][4];
    #pragma unroll
    for (int r = 0; r < 8; r++)
        #pragma unroll
        for (int j = 0; j < 4; j++) acc[r][j] = 0ull;

    for (int kt = 0; kt < K; kt += C_KC) {
        // y tile: y = dis*agg + dinv*x computed on load
        for (int idx = tid; idx < 64 * C_KC; idx += 256) {
            int nn = idx / C_KC, kk = idx % C_KC;
            int node = n0 + nn;
            float v = 0.f;
            if (node < n) {
                int gk = koff + kt + kk;
                v = sdis[nn] * g_agg[node * FEAT + gk] + sdinv[nn] * x[node * FEAT + gk];
            }
            ys[kk][nn] = v;
        }
        // W tile
        #pragma unroll
        for (int it = 0; it < C_KC; it++)
            Wt[it][tid] = W[(kt + it) * 256 + tid];
        __syncthreads();

        #pragma unroll
        for (int kk = 0; kk < C_KC; kk++) {
            float4 a0 = *reinterpret_cast<const float4*>(&ys[kk][tm0]);
            float4 a1 = *reinterpret_cast<const float4*>(&ys[kk][tm0 + 4]);
            ulonglong2 w0 = *reinterpret_cast<const ulonglong2*>(&Wt[kk][tn0]);
            ulonglong2 w1 = *reinterpret_cast<const ulonglong2*>(&Wt[kk][tn0 + 4]);
            float av[8] = {a0.x, a0.y, a0.z, a0.w, a1.x, a1.y, a1.z, a1.w};
            #pragma unroll
            for (int r = 0; r < 8; r++) {
                unsigned long long ad = dup2(av[r]);
                fma2(acc[r][0], ad, w0.x);
                fma2(acc[r][1], ad, w0.y);
                fma2(acc[r][2], ad, w1.x);
                fma2(acc[r][3], ad, w1.y);
            }
        }
        __syncthreads();
    }

    float4 bv0 = *reinterpret_cast<const float4*>(&bias[tn0]);
    float4 bv1 = *reinterpret_cast<const float4*>(&bias[tn0 + 4]);
    #pragma unroll
    for (int r = 0; r < 8; r++) {
        int node = n0 + tm0 + r;
        if (node >= n) continue;
        float2 v0 = unpack2(acc[r][0]);
        float2 v1 = unpack2(acc[r][1]);
        float2 v2 = unpack2(acc[r][2]);
        float2 v3 = unpack2(acc[r][3]);
        float4 o0 = make_float4(fmaxf(v0.x + bv0.x, 0.f), fmaxf(v0.y + bv0.y, 0.f),
                                fmaxf(v1.x + bv0.z, 0.f), fmaxf(v1.y + bv0.w, 0.f));
        float4 o1 = make_float4(fmaxf(v2.x + bv1.x, 0.f), fmaxf(v2.y + bv1.y, 0.f),
                                fmaxf(v3.x + bv1.z, 0.f), fmaxf(v3.y + bv1.w, 0.f));
        float* dst = &g_sf[(size_t)node * 512 + part * 256 + tn0];
        *reinterpret_cast<float4*>(dst)     = o0;
        *reinterpret_cast<float4*>(dst + 4) = o1;
    }
}

// ---------------- phase 7: fused QK projection + 2x2 attention ----------------
// 32 nodes (64 tokens) per block. smem:
//   As  [256][68]  (comb, K-major, persistent)   17408 f
//   Bs  [32][132]  (Wq/Wk k-tile)                 4224 f
//   Out [64][520]  (q cols 0:256, k cols 256:512) 33280 f
//   dvS [64*8], red[64]
#define D_SMEM_FLOATS (256*68 + 32*132 + 64*520 + 512 + 64)
extern __shared__ float dsm[];

__global__ __launch_bounds__(256, 1) void k_attn(
        const float* __restrict__ ipw, const float* __restrict__ ipb, int n) {
    float* As  = dsm;
    float* Bs  = As + 256 * 68;
    float* Out = Bs + 32 * 132;
    float* dvS = Out + 64 * 520;
    float* red = dvS + 512;

    int tid = threadIdx.x;
    int n0 = blockIdx.x * 32;

    // load comb (s,f rows) transposed into As[k][tok], tok = local_node*2 + t
    #pragma unroll 4
    for (int i = 0; i < 64; i++) {
        int node = n0 + (i >> 1);
        float v = (node < n) ? g_sf[(size_t)node * 512 + (i & 1) * 256 + tid] : 0.f;
        As[tid * 68 + i] = v;
    }
    __syncthreads();

    int tm0 = (tid >> 5) * 8;   // token base
    int tn0 = (tid & 31) * 4;   // col base within 128-chunk

    for (int chunk = 0; chunk < 4; chunk++) {
        int r0 = chunk * 128;
        unsigned long long acc[8][2];
        #pragma unroll
        for (int r = 0; r < 8; r++) { acc[r][0] = 0ull; acc[r][1] = 0ull; }

        for (int kt = 0; kt < 256; kt += 32) {
            #pragma unroll
            for (int it = 0; it < 16; it++) {
                int idx = it * 256 + tid;
                int rr = idx >> 5, kk = idx & 31;
                Bs[kk * 132 + rr] = ipw[(r0 + rr) * 256 + kt + kk];
            }
            __syncthreads();
            #pragma unroll
            for (int kk = 0; kk < 32; kk++) {
                const float* as = &As[(kt + kk) * 68 + tm0];
                float4 a0 = *reinterpret_cast<const float4*>(as);
                float4 a1 = *reinterpret_cast<const float4*>(as + 4);
                ulonglong2 b = *reinterpret_cast<const ulonglong2*>(&Bs[kk * 132 + tn0]);
                float av[8] = {a0.x, a0.y, a0.z, a0.w, a1.x, a1.y, a1.z, a1.w};
                #pragma unroll
                for (int r = 0; r < 8; r++) {
                    unsigned long long ad = dup2(av[r]);
                    fma2(acc[r][0], ad, b.x);
                    fma2(acc[r][1], ad, b.y);
                }
            }
            __syncthreads();
        }
        float4 bv = *reinterpret_cast<const float4*>(&ipb[r0 + tn0]);
        #pragma unroll
        for (int r = 0; r < 8; r++) {
            float2 lo = unpack2(acc[r][0]);
            float2 hi = unpack2(acc[r][1]);
            float4 o = make_float4(lo.x + bv.x, lo.y + bv.y, hi.x + bv.z, hi.y + bv.w);
            *reinterpret_cast<float4*>(&Out[(tm0 + r) * 520 + r0 + tn0]) = o;
        }
    }

    // dv_{tok,h} = comb_tok . u_h + c_h   (512 dots, 2 per thread)
    #pragma unroll
    for (int rep = 0; rep < 2; rep++) {
        int di = rep * 256 + tid;
        int tok = di >> 3, h = di & 7;
        float a = 0.f;
        #pragma unroll 8
        for (int k = 0; k < 256; k++) a += As[k * 68 + tok] * g_u[h * 256 + k];
        dvS[tok * 8 + h] = a + g_c[h];
    }
    __syncthreads();

    // per (node, head) 2x2 attention
    int node = tid >> 3, h = tid & 7;
    const float* q0 = &Out[(node * 2 + 0) * 520 + h * 32];
    const float* q1 = &Out[(node * 2 + 1) * 520 + h * 32];
    const float* k0 = &Out[(node * 2 + 0) * 520 + 256 + h * 32];
    const float* k1 = &Out[(node * 2 + 1) * 520 + 256 + h * 32];
    float s00 = 0.f, s01 = 0.f, s10 = 0.f, s11 = 0.f;
    #pragma unroll
    for (int d = 0; d < 32; d++) {
        float a0 = q0[d], a1 = q1[d], b0 = k0[d], b1 = k1[d];
        s00 += a0 * b0; s01 += a0 * b1; s10 += a1 * b0; s11 += a1 * b1;
    }
    const float scale = 0.17677669529663687f;  // 1/sqrt(32)
    s00 *= scale; s01 *= scale; s10 *= scale; s11 *= scale;
    float m0 = fmaxf(s00, s01), m1 = fmaxf(s10, s11);
    float e00 = expf(s00 - m0), e01 = expf(s01 - m0);
    float e10 = expf(s10 - m1), e11 = expf(s11 - m1);
    float d0 = e00 + e01, d1 = e10 + e11;
    float a00 = e00 / d0, a01 = e01 / d0;
    float a10 = e10 / d1, a11 = e11 / d1;
    float dv0 = dvS[node * 16 + h];
    float dv1 = dvS[node * 16 + 8 + h];
    float contrib = 0.5f * ((a00 + a10) * dv0 + (a01 + a11) * dv1);
    if (n0 + node >= n) contrib = 0.f;

    // block reduce -> one atomic
    #pragma unroll
    for (int off = 16; off; off >>= 1)
        contrib += __shfl_xor_sync(0xffffffffu, contrib, off);
    if ((tid & 31) == 0) red[tid >> 5] = contrib;
    __syncthreads();
    if (tid == 0) {
        float s = 0.f;
        #pragma unroll
        for (int w = 0; w < 8; w++) s += red[w];
        atomicAdd(&g_acc[0], s);
    }
}

// ---------------- phase 8: final scalar ----------------
__global__ void k_final(float* __restrict__ out, int n) {
    out[0] = g_acc[0] / (float)n + g_konst[0];
}

// ---------------- launch ----------------
extern "C" void kernel_launch(void* const* d_in, const int* in_sizes, int n_in,
                              void* d_out, int out_size) {
    const float* x   = (const float*)d_in[0];
    const int*   ei  = (const int*)d_in[1];     // int32 (JAX x64 disabled)
    const float* W_s = (const float*)d_in[2];
    const float* b_s = (const float*)d_in[3];
    const float* W_f = (const float*)d_in[4];
    const float* b_f = (const float*)d_in[5];
    const float* ipw = (const float*)d_in[6];
    const float* ipb = (const float*)d_in[7];
    const float* opw = (const float*)d_in[8];
    const float* opb = (const float*)d_in[9];
    const float* ow  = (const float*)d_in[10];
    const float* ob  = (const float*)d_in[11];

    int n = in_sizes[0] / FEAT;
    int E = in_sizes[1] / 2;

    k_zero<<<1024, 256>>>(n);
    k_deg<<<(E + 255) / 256, 256>>>(ei, E);
    k_dis<<<(n + 255) / 256, 256>>>(n);
    k_z<<<n, 256>>>(x);
    k_edge<<<(E + 7) / 8, 256>>>(ei, E);
    k_prep<<<1, 256>>>(ipw, ipb, opw, opb, ow, ob);

    dim3 gc((n + 63) / 64, 2);
    k_gcn<<<gc, 256>>>(x, W_s, b_s, W_f, b_f, n);

    int dsm_bytes = D_SMEM_FLOATS * 4;
    cudaFuncSetAttribute(k_attn, cudaFuncAttributeMaxDynamicSharedMemorySize, dsm_bytes);
    k_attn<<<(n + 31) / 32, 256, dsm_bytes>>>(ipw, ipb, n);

    k_final<<<1, 1>>>((float*)d_out, n);
}

// round 3
// speedup vs baseline: 1.1187x; 1.1187x over previous
#include <cuda_runtime.h>

#define N_NODES_MAX 50000
#define E_MAX 1600000
#define FEAT 300
#define HID 256

// ---------------- device scratch (no allocations allowed) ----------------
__device__ int   g_degi[N_NODES_MAX];
__device__ int   g_off [N_NODES_MAX + 1];
__device__ int   g_cur [N_NODES_MAX];
__device__ int   g_srcs[E_MAX];
__device__ __align__(16) float g_dis [N_NODES_MAX];
__device__ __align__(16) float g_dinv[N_NODES_MAX];
__device__ __align__(16) float g_agg [N_NODES_MAX * FEAT];   // sum_e dis[src]*x[src]
__device__ __align__(16) float g_sf  [N_NODES_MAX * 2 * HID];// per node: [0:256]=s, [256:512]=f
__device__ __align__(16) float g_u   [8 * 256];              // folded V-proj vectors per head
__device__ __align__(16) float g_c   [8];                    // folded V-bias per head
__device__ float g_konst[1];                   // out_proj_b . out_w + out_b
__device__ float g_acc [1];                    // sum of per-node contributions

// ---------------- f32x2 helpers (Blackwell packed fp32 pipe) ----------------
__device__ __forceinline__ void fma2(unsigned long long &d,
                                     unsigned long long a,
                                     unsigned long long b) {
    asm("fma.rn.f32x2 %0, %1, %2, %0;" : "+l"(d) : "l"(a), "l"(b));
}
__device__ __forceinline__ unsigned long long dup2(float x) {
    unsigned long long r;
    asm("mov.b64 %0, {%1, %1};" : "=l"(r) : "f"(x));
    return r;
}
__device__ __forceinline__ float2 unpack2(unsigned long long v) {
    float2 r;
    asm("mov.b64 {%0, %1}, %2;" : "=f"(r.x), "=f"(r.y) : "l"(v));
    return r;
}

// ---------------- phase 0: zero degree + acc ----------------
__global__ void k_zero(int n) {
    int i = blockIdx.x * blockDim.x + threadIdx.x;
    if (i < n) g_degi[i] = 0;
    if (i == 0) g_acc[0] = 0.f;
}

// ---------------- phase 1: in-degree (int atomics) ----------------
__global__ void k_deg(const int* __restrict__ ei, int E) {
    int i = blockIdx.x * blockDim.x + threadIdx.x;
    if (i < E) atomicAdd(&g_degi[ei[E + i]], 1);
}

// ---------------- phase 2: normalizers ----------------
__global__ void k_dis(int n) {
    int i = blockIdx.x * blockDim.x + threadIdx.x;
    if (i < n) {
        float d = 1.0f + (float)g_degi[i];
        g_dis[i]  = rsqrtf(d);
        g_dinv[i] = 1.0f / d;
    }
}

// ---------------- phase 3: exclusive prefix scan (single block) ----------------
__global__ void k_scan(int n) {
    __shared__ int sh[1024];
    int t = threadIdx.x;
    int chunk = (n + 1023) >> 10;
    int start = t * chunk;
    int end   = min(start + chunk, n);
    int sum = 0;
    for (int i = start; i < end; i++) sum += g_degi[i];
    sh[t] = sum;
    __syncthreads();
    // inclusive Hillis-Steele scan over 1024 partials
    for (int off = 1; off < 1024; off <<= 1) {
        int v = (t >= off) ? sh[t - off] : 0;
        __syncthreads();
        sh[t] += v;
        __syncthreads();
    }
    int off = (t > 0) ? sh[t - 1] : 0;
    for (int i = start; i < end; i++) {
        g_off[i] = off;
        g_cur[i] = off;
        off += g_degi[i];
    }
    if (start < n && end == n) g_off[n] = off;
}

// ---------------- phase 4: scatter src ids into CSR buckets ----------------
__global__ void k_scatter(const int* __restrict__ ei, int E) {
    int i = blockIdx.x * blockDim.x + threadIdx.x;
    if (i >= E) return;
    int s = ei[i];
    int d = ei[E + i];
    int pos = atomicAdd(&g_cur[d], 1);
    g_srcs[pos] = s;
}

// ---------------- phase 5: gather-aggregate (1 warp / node, regs accumulate) ----
__global__ __launch_bounds__(256) void k_gather(const float* __restrict__ x, int n) {
    int w    = (blockIdx.x * blockDim.x + threadIdx.x) >> 5;
    int lane = threadIdx.x & 31;
    if (w >= n) return;
    int beg = g_off[w], end = g_off[w + 1];

    float4 a0 = make_float4(0.f, 0.f, 0.f, 0.f);
    float4 a1 = a0, a2 = a0;

    for (int base = beg; base < end; base += 32) {
        int cnt = min(32, end - base);
        int   s_l = 0;
        float w_l = 0.f;
        if (lane < cnt) {
            s_l = g_srcs[base + lane];
            w_l = g_dis[s_l];
        }
        for (int k = 0; k < cnt; k++) {
            int   s  = __shfl_sync(0xffffffffu, s_l, k);
            float wt = __shfl_sync(0xffffffffu, w_l, k);
            const float4* xr = reinterpret_cast<const float4*>(x + (size_t)s * FEAT);
            float4 v0 = __ldg(&xr[lane]);
            float4 v1 = __ldg(&xr[lane + 32]);
            a0.x += wt * v0.x; a0.y += wt * v0.y; a0.z += wt * v0.z; a0.w += wt * v0.w;
            a1.x += wt * v1.x; a1.y += wt * v1.y; a1.z += wt * v1.z; a1.w += wt * v1.w;
            if (lane < 11) {
                float4 v2 = __ldg(&xr[lane + 64]);
                a2.x += wt * v2.x; a2.y += wt * v2.y; a2.z += wt * v2.z; a2.w += wt * v2.w;
            }
        }
    }
    float4* ar = reinterpret_cast<float4*>(g_agg + (size_t)w * FEAT);
    ar[lane]      = a0;
    ar[lane + 32] = a1;
    if (lane < 11) ar[lane + 64] = a2;
}

// ---------------- phase 6: fold out_proj/out_w into per-head vectors ----------------
__global__ void k_prep(const float* __restrict__ ipw, const float* __restrict__ ipb,
                       const float* __restrict__ opw, const float* __restrict__ opb,
                       const float* __restrict__ ow,  const float* __restrict__ ob) {
    __shared__ float vout[256];
    int t = threadIdx.x;  // 256 threads
    float acc = 0.f;
    for (int j = 0; j < 256; j++) acc += opw[j * 256 + t] * ow[j];
    vout[t] = acc;
    __syncthreads();
    #pragma unroll
    for (int h = 0; h < 8; h++) {
        float a = 0.f;
        #pragma unroll 8
        for (int d = 0; d < 32; d++)
            a += ipw[(512 + h * 32 + d) * 256 + t] * vout[h * 32 + d];
        g_u[h * 256 + t] = a;
    }
    if (t < 8) {
        float c = 0.f;
        for (int d = 0; d < 32; d++) c += ipb[512 + t * 32 + d] * vout[t * 32 + d];
        g_c[t] = c;
    }
    if (t == 0) {
        float c = 0.f;
        for (int j = 0; j < 256; j++) c += opb[j] * ow[j];
        g_konst[0] = c + ob[0];
    }
}

// ---------------- phase 7: GCN GEMM  s/f = relu(y @ W + b) ----------------
// grid.y = 0 -> s (K=100, W_s), grid.y = 1 -> f (K=200, W_f)
#define C_KC 25
__global__ __launch_bounds__(256) void k_gcn(
        const float* __restrict__ x,
        const float* __restrict__ Wsg, const float* __restrict__ bsg,
        const float* __restrict__ Wfg, const float* __restrict__ bfg, int n) {
    __shared__ __align__(16) float ys[C_KC][68];     // transposed y tile [k][node]
    __shared__ __align__(16) float Wt[C_KC][260];    // W tile [k][col]
    __shared__ float sdis[64], sdinv[64];

    int part = blockIdx.y;
    const float* W    = part ? Wfg : Wsg;
    const float* bias = part ? bfg : bsg;
    int K    = part ? 200 : 100;
    int koff = part ? 100 : 0;
    int n0  = blockIdx.x * 64;
    int tid = threadIdx.x;

    if (tid < 64) {
        int nn = n0 + tid;
        sdis[tid]  = (nn < n) ? g_dis[nn]  : 0.f;
        sdinv[tid] = (nn < n) ? g_dinv[nn] : 0.f;
    }
    __syncthreads();

    int tm0 = (tid >> 5) * 8;   // node row base (warp-uniform -> broadcast LDS)
    int tn0 = (tid & 31) * 8;   // col base

    unsigned long long acc[8][4];
    #pragma unroll
    for (int r = 0; r < 8; r++)
        #pragma unroll
        for (int j = 0; j < 4; j++) acc[r][j] = 0ull;

    for (int kt = 0; kt < K; kt += C_KC) {
        // y tile: y = dis*agg + dinv*x computed on load
        for (int idx = tid; idx < 64 * C_KC; idx += 256) {
            int nn = idx / C_KC, kk = idx % C_KC;
            int node = n0 + nn;
            float v = 0.f;
            if (node < n) {
                int gk = koff + kt + kk;
                v = sdis[nn] * g_agg[node * FEAT + gk] + sdinv[nn] * x[node * FEAT + gk];
            }
            ys[kk][nn] = v;
        }
        // W tile
        #pragma unroll
        for (int it = 0; it < C_KC; it++)
            Wt[it][tid] = W[(kt + it) * 256 + tid];
        __syncthreads();

        #pragma unroll
        for (int kk = 0; kk < C_KC; kk++) {
            float4 a0 = *reinterpret_cast<const float4*>(&ys[kk][tm0]);
            float4 a1 = *reinterpret_cast<const float4*>(&ys[kk][tm0 + 4]);
            ulonglong2 w0 = *reinterpret_cast<const ulonglong2*>(&Wt[kk][tn0]);
            ulonglong2 w1 = *reinterpret_cast<const ulonglong2*>(&Wt[kk][tn0 + 4]);
            float av[8] = {a0.x, a0.y, a0.z, a0.w, a1.x, a1.y, a1.z, a1.w};
            #pragma unroll
            for (int r = 0; r < 8; r++) {
                unsigned long long ad = dup2(av[r]);
                fma2(acc[r][0], ad, w0.x);
                fma2(acc[r][1], ad, w0.y);
                fma2(acc[r][2], ad, w1.x);
                fma2(acc[r][3], ad, w1.y);
            }
        }
        __syncthreads();
    }

    float4 bv0 = *reinterpret_cast<const float4*>(&bias[tn0]);
    float4 bv1 = *reinterpret_cast<const float4*>(&bias[tn0 + 4]);
    #pragma unroll
    for (int r = 0; r < 8; r++) {
        int node = n0 + tm0 + r;
        if (node >= n) continue;
        float2 v0 = unpack2(acc[r][0]);
        float2 v1 = unpack2(acc[r][1]);
        float2 v2 = unpack2(acc[r][2]);
        float2 v3 = unpack2(acc[r][3]);
        float4 o0 = make_float4(fmaxf(v0.x + bv0.x, 0.f), fmaxf(v0.y + bv0.y, 0.f),
                                fmaxf(v1.x + bv0.z, 0.f), fmaxf(v1.y + bv0.w, 0.f));
        float4 o1 = make_float4(fmaxf(v2.x + bv1.x, 0.f), fmaxf(v2.y + bv1.y, 0.f),
                                fmaxf(v3.x + bv1.z, 0.f), fmaxf(v3.y + bv1.w, 0.f));
        float* dst = &g_sf[(size_t)node * 512 + part * 256 + tn0];
        *reinterpret_cast<float4*>(dst)     = o0;
        *reinterpret_cast<float4*>(dst + 4) = o1;
    }
}

// ---------------- phase 8: fused QK projection + 2x2 attention ----------------
// 32 nodes (64 tokens) per block.
#define D_SMEM_FLOATS (256*68 + 32*132 + 64*520 + 512 + 64)
extern __shared__ float dsm[];

__global__ __launch_bounds__(256, 1) void k_attn(
        const float* __restrict__ ipw, const float* __restrict__ ipb, int n) {
    float* As  = dsm;
    float* Bs  = As + 256 * 68;
    float* Out = Bs + 32 * 132;
    float* dvS = Out + 64 * 520;
    float* red = dvS + 512;

    int tid = threadIdx.x;
    int n0 = blockIdx.x * 32;

    // load comb (s,f rows) transposed into As[k][tok], tok = local_node*2 + t
    #pragma unroll 4
    for (int i = 0; i < 64; i++) {
        int node = n0 + (i >> 1);
        float v = (node < n) ? g_sf[(size_t)node * 512 + (i & 1) * 256 + tid] : 0.f;
        As[tid * 68 + i] = v;
    }
    __syncthreads();

    int tm0 = (tid >> 5) * 8;   // token base
    int tn0 = (tid & 31) * 4;   // col base within 128-chunk

    for (int chunk = 0; chunk < 4; chunk++) {
        int r0 = chunk * 128;
        unsigned long long acc[8][2];
        #pragma unroll
        for (int r = 0; r < 8; r++) { acc[r][0] = 0ull; acc[r][1] = 0ull; }

        for (int kt = 0; kt < 256; kt += 32) {
            #pragma unroll
            for (int it = 0; it < 16; it++) {
                int idx = it * 256 + tid;
                int rr = idx >> 5, kk = idx & 31;
                Bs[kk * 132 + rr] = ipw[(r0 + rr) * 256 + kt + kk];
            }
            __syncthreads();
            #pragma unroll
            for (int kk = 0; kk < 32; kk++) {
                const float* as = &As[(kt + kk) * 68 + tm0];
                float4 a0 = *reinterpret_cast<const float4*>(as);
                float4 a1 = *reinterpret_cast<const float4*>(as + 4);
                ulonglong2 b = *reinterpret_cast<const ulonglong2*>(&Bs[kk * 132 + tn0]);
                float av[8] = {a0.x, a0.y, a0.z, a0.w, a1.x, a1.y, a1.z, a1.w};
                #pragma unroll
                for (int r = 0; r < 8; r++) {
                    unsigned long long ad = dup2(av[r]);
                    fma2(acc[r][0], ad, b.x);
                    fma2(acc[r][1], ad, b.y);
                }
            }
            __syncthreads();
        }
        float4 bv = *reinterpret_cast<const float4*>(&ipb[r0 + tn0]);
        #pragma unroll
        for (int r = 0; r < 8; r++) {
            float2 lo = unpack2(acc[r][0]);
            float2 hi = unpack2(acc[r][1]);
            float4 o = make_float4(lo.x + bv.x, lo.y + bv.y, hi.x + bv.z, hi.y + bv.w);
            *reinterpret_cast<float4*>(&Out[(tm0 + r) * 520 + r0 + tn0]) = o;
        }
    }

    // dv_{tok,h} = comb_tok . u_h + c_h   (512 dots, 2 per thread)
    #pragma unroll
    for (int rep = 0; rep < 2; rep++) {
        int di = rep * 256 + tid;
        int tok = di >> 3, h = di & 7;
        float a = 0.f;
        #pragma unroll 8
        for (int k = 0; k < 256; k++) a += As[k * 68 + tok] * g_u[h * 256 + k];
        dvS[tok * 8 + h] = a + g_c[h];
    }
    __syncthreads();

    // per (node, head) 2x2 attention
    int node = tid >> 3, h = tid & 7;
    const float* q0 = &Out[(node * 2 + 0) * 520 + h * 32];
    const float* q1 = &Out[(node * 2 + 1) * 520 + h * 32];
    const float* k0 = &Out[(node * 2 + 0) * 520 + 256 + h * 32];
    const float* k1 = &Out[(node * 2 + 1) * 520 + 256 + h * 32];
    float s00 = 0.f, s01 = 0.f, s10 = 0.f, s11 = 0.f;
    #pragma unroll
    for (int d = 0; d < 32; d++) {
        float a0 = q0[d], a1 = q1[d], b0 = k0[d], b1 = k1[d];
        s00 += a0 * b0; s01 += a0 * b1; s10 += a1 * b0; s11 += a1 * b1;
    }
    const float scale = 0.17677669529663687f;  // 1/sqrt(32)
    s00 *= scale; s01 *= scale; s10 *= scale; s11 *= scale;
    float m0 = fmaxf(s00, s01), m1 = fmaxf(s10, s11);
    float e00 = expf(s00 - m0), e01 = expf(s01 - m0);
    float e10 = expf(s10 - m1), e11 = expf(s11 - m1);
    float d0 = e00 + e01, d1 = e10 + e11;
    float a00 = e00 / d0, a01 = e01 / d0;
    float a10 = e10 / d1, a11 = e11 / d1;
    float dv0 = dvS[node * 16 + h];
    float dv1 = dvS[node * 16 + 8 + h];
    float contrib = 0.5f * ((a00 + a10) * dv0 + (a01 + a11) * dv1);
    if (n0 + node >= n) contrib = 0.f;

    // block reduce -> one atomic
    #pragma unroll
    for (int off = 16; off; off >>= 1)
        contrib += __shfl_xor_sync(0xffffffffu, contrib, off);
    if ((tid & 31) == 0) red[tid >> 5] = contrib;
    __syncthreads();
    if (tid == 0) {
        float s = 0.f;
        #pragma unroll
        for (int w = 0; w < 8; w++) s += red[w];
        atomicAdd(&g_acc[0], s);
    }
}

// ---------------- phase 9: final scalar ----------------
__global__ void k_final(float* __restrict__ out, int n) {
    out[0] = g_acc[0] / (float)n + g_konst[0];
}

// ---------------- launch ----------------
extern "C" void kernel_launch(void* const* d_in, const int* in_sizes, int n_in,
                              void* d_out, int out_size) {
    const float* x   = (const float*)d_in[0];
    const int*   ei  = (const int*)d_in[1];     // int32 (JAX x64 disabled)
    const float* W_s = (const float*)d_in[2];
    const float* b_s = (const float*)d_in[3];
    const float* W_f = (const float*)d_in[4];
    const float* b_f = (const float*)d_in[5];
    const float* ipw = (const float*)d_in[6];
    const float* ipb = (const float*)d_in[7];
    const float* opw = (const float*)d_in[8];
    const float* opb = (const float*)d_in[9];
    const float* ow  = (const float*)d_in[10];
    const float* ob  = (const float*)d_in[11];

    int n = in_sizes[0] / FEAT;
    int E = in_sizes[1] / 2;

    k_zero<<<(n + 255) / 256, 256>>>(n);
    k_deg<<<(E + 255) / 256, 256>>>(ei, E);
    k_dis<<<(n + 255) / 256, 256>>>(n);
    k_scan<<<1, 1024>>>(n);
    k_scatter<<<(E + 255) / 256, 256>>>(ei, E);
    k_gather<<<(n + 7) / 8, 256>>>(x, n);
    k_prep<<<1, 256>>>(ipw, ipb, opw, opb, ow, ob);

    dim3 gc((n + 63) / 64, 2);
    k_gcn<<<gc, 256>>>(x, W_s, b_s, W_f, b_f, n);

    int dsm_bytes = D_SMEM_FLOATS * 4;
    cudaFuncSetAttribute(k_attn, cudaFuncAttributeMaxDynamicSharedMemorySize, dsm_bytes);
    k_attn<<<(n + 31) / 32, 256, dsm_bytes>>>(ipw, ipb, n);

    k_final<<<1, 1>>>((float*)d_out, n);
}

// round 4
// speedup vs baseline: 1.2782x; 1.1426x over previous
#include <cuda_runtime.h>

#define N_NODES_MAX 50000
#define E_MAX 1600000
#define FEAT 300
#define HID 256

// ---------------- device scratch (no allocations allowed) ----------------
__device__ int   g_degi[N_NODES_MAX];
__device__ int   g_off [N_NODES_MAX + 1];
__device__ int   g_cur [N_NODES_MAX];
__device__ int   g_srcs[E_MAX];
__device__ int   g_bsum[256];
__device__ int   g_bpre[256];
__device__ __align__(16) float g_dis [N_NODES_MAX];
__device__ __align__(16) float g_dinv[N_NODES_MAX];
__device__ __align__(16) float g_agg [N_NODES_MAX * FEAT];   // sum_e dis[src]*x[src]
__device__ __align__(16) float g_sf  [N_NODES_MAX * 2 * HID];// per node: [0:256]=s, [256:512]=f
__device__ __align__(16) float g_u   [8 * 256];              // folded V-proj vectors per head
__device__ __align__(16) float g_c   [8];                    // folded V-bias per head
__device__ float g_konst[1];                   // out_proj_b . out_w + out_b
__device__ float g_acc [1];                    // sum of per-node contributions

// ---------------- f32x2 helpers (Blackwell packed fp32 pipe) ----------------
__device__ __forceinline__ void fma2(unsigned long long &d,
                                     unsigned long long a,
                                     unsigned long long b) {
    asm("fma.rn.f32x2 %0, %1, %2, %0;" : "+l"(d) : "l"(a), "l"(b));
}
__device__ __forceinline__ unsigned long long dup2(float x) {
    unsigned long long r;
    asm("mov.b64 %0, {%1, %1};" : "=l"(r) : "f"(x));
    return r;
}
__device__ __forceinline__ float2 unpack2(unsigned long long v) {
    float2 r;
    asm("mov.b64 {%0, %1}, %2;" : "=f"(r.x), "=f"(r.y) : "l"(v));
    return r;
}

// ---------------- phase 0: zero degree + acc ----------------
__global__ void k_zero(int n) {
    int i = blockIdx.x * blockDim.x + threadIdx.x;
    if (i < n) g_degi[i] = 0;
    if (i == 0) g_acc[0] = 0.f;
}

// ---------------- phase 1: in-degree (int atomics) ----------------
__global__ void k_deg(const int* __restrict__ ei, int E) {
    int i = blockIdx.x * blockDim.x + threadIdx.x;
    if (i < E) atomicAdd(&g_degi[ei[E + i]], 1);
}

// ---------------- phase 2: normalizers ----------------
__global__ void k_dis(int n) {
    int i = blockIdx.x * blockDim.x + threadIdx.x;
    if (i < n) {
        float d = 1.0f + (float)g_degi[i];
        g_dis[i]  = rsqrtf(d);
        g_dinv[i] = 1.0f / d;
    }
}

// ---------------- phase 3a: per-256-block sums ----------------
__global__ void k_scanA(int n) {
    __shared__ int sh[8];
    int i = blockIdx.x * 256 + threadIdx.x;
    int v = (i < n) ? g_degi[i] : 0;
    #pragma unroll
    for (int off = 16; off; off >>= 1) v += __shfl_xor_sync(0xffffffffu, v, off);
    if ((threadIdx.x & 31) == 0) sh[threadIdx.x >> 5] = v;
    __syncthreads();
    if (threadIdx.x == 0) {
        int s = 0;
        #pragma unroll
        for (int w = 0; w < 8; w++) s += sh[w];
        g_bsum[blockIdx.x] = s;
    }
}

// ---------------- phase 3b: scan the block sums (<=256 of them) ----------------
__global__ void k_scanB(int nb, int n) {
    __shared__ int sh[256];
    int t = threadIdx.x;
    int v = (t < nb) ? g_bsum[t] : 0;
    sh[t] = v;
    __syncthreads();
    #pragma unroll
    for (int off = 1; off < 256; off <<= 1) {
        int u = (t >= off) ? sh[t - off] : 0;
        __syncthreads();
        sh[t] += u;
        __syncthreads();
    }
    if (t < nb) g_bpre[t] = sh[t] - v;   // exclusive
    if (t == nb - 1) g_off[n] = sh[t];   // total edge count
}

// ---------------- phase 3c: per-block offsets ----------------
__global__ void k_scanC(int n) {
    __shared__ int sh[256];
    int t = threadIdx.x;
    int i = blockIdx.x * 256 + t;
    int v = (i < n) ? g_degi[i] : 0;
    sh[t] = v;
    __syncthreads();
    #pragma unroll
    for (int off = 1; off < 256; off <<= 1) {
        int u = (t >= off) ? sh[t - off] : 0;
        __syncthreads();
        sh[t] += u;
        __syncthreads();
    }
    if (i < n) {
        int off = g_bpre[blockIdx.x] + sh[t] - v;  // global exclusive prefix
        g_off[i] = off;
        g_cur[i] = off;
    }
}

// ---------------- phase 4: scatter src ids into CSR buckets ----------------
__global__ void k_scatter(const int* __restrict__ ei, int E) {
    int i = blockIdx.x * blockDim.x + threadIdx.x;
    if (i >= E) return;
    int s = ei[i];
    int d = ei[E + i];
    int pos = atomicAdd(&g_cur[d], 1);
    g_srcs[pos] = s;
}

// ---------------- phase 5: gather-aggregate (1 warp / node, regs accumulate) ----
__global__ __launch_bounds__(256) void k_gather(const float* __restrict__ x, int n) {
    int w    = (blockIdx.x * blockDim.x + threadIdx.x) >> 5;
    int lane = threadIdx.x & 31;
    if (w >= n) return;
    int beg = g_off[w], end = g_off[w + 1];

    float4 a0 = make_float4(0.f, 0.f, 0.f, 0.f);
    float4 a1 = a0, a2 = a0;

    for (int base = beg; base < end; base += 32) {
        int cnt = min(32, end - base);
        int   s_l = 0;
        float w_l = 0.f;
        if (lane < cnt) {
            s_l = g_srcs[base + lane];
            w_l = g_dis[s_l];
        }
        if (cnt == 32) {
            #pragma unroll 4
            for (int k = 0; k < 32; k++) {
                int   s  = __shfl_sync(0xffffffffu, s_l, k);
                float wt = __shfl_sync(0xffffffffu, w_l, k);
                const float4* xr = reinterpret_cast<const float4*>(x + (size_t)s * FEAT);
                float4 v0 = __ldg(&xr[lane]);
                float4 v1 = __ldg(&xr[lane + 32]);
                a0.x += wt * v0.x; a0.y += wt * v0.y; a0.z += wt * v0.z; a0.w += wt * v0.w;
                a1.x += wt * v1.x; a1.y += wt * v1.y; a1.z += wt * v1.z; a1.w += wt * v1.w;
                if (lane < 11) {
                    float4 v2 = __ldg(&xr[lane + 64]);
                    a2.x += wt * v2.x; a2.y += wt * v2.y; a2.z += wt * v2.z; a2.w += wt * v2.w;
                }
            }
        } else {
            for (int k = 0; k < cnt; k++) {
                int   s  = __shfl_sync(0xffffffffu, s_l, k);
                float wt = __shfl_sync(0xffffffffu, w_l, k);
                const float4* xr = reinterpret_cast<const float4*>(x + (size_t)s * FEAT);
                float4 v0 = __ldg(&xr[lane]);
                float4 v1 = __ldg(&xr[lane + 32]);
                a0.x += wt * v0.x; a0.y += wt * v0.y; a0.z += wt * v0.z; a0.w += wt * v0.w;
                a1.x += wt * v1.x; a1.y += wt * v1.y; a1.z += wt * v1.z; a1.w += wt * v1.w;
                if (lane < 11) {
                    float4 v2 = __ldg(&xr[lane + 64]);
                    a2.x += wt * v2.x; a2.y += wt * v2.y; a2.z += wt * v2.z; a2.w += wt * v2.w;
                }
            }
        }
    }
    float4* ar = reinterpret_cast<float4*>(g_agg + (size_t)w * FEAT);
    ar[lane]      = a0;
    ar[lane + 32] = a1;
    if (lane < 11) ar[lane + 64] = a2;
}

// ---------------- phase 6: fold out_proj/out_w into per-head vectors ----------------
__global__ void k_prep(const float* __restrict__ ipw, const float* __restrict__ ipb,
                       const float* __restrict__ opw, const float* __restrict__ opb,
                       const float* __restrict__ ow,  const float* __restrict__ ob) {
    __shared__ float vout[256];
    int t = threadIdx.x;  // 256 threads
    float acc = 0.f;
    for (int j = 0; j < 256; j++) acc += opw[j * 256 + t] * ow[j];
    vout[t] = acc;
    __syncthreads();
    #pragma unroll
    for (int h = 0; h < 8; h++) {
        float a = 0.f;
        #pragma unroll 8
        for (int d = 0; d < 32; d++)
            a += ipw[(512 + h * 32 + d) * 256 + t] * vout[h * 32 + d];
        g_u[h * 256 + t] = a;
    }
    if (t < 8) {
        float c = 0.f;
        for (int d = 0; d < 32; d++) c += ipb[512 + t * 32 + d] * vout[t * 32 + d];
        g_c[t] = c;
    }
    if (t == 0) {
        float c = 0.f;
        for (int j = 0; j < 256; j++) c += opb[j] * ow[j];
        g_konst[0] = c + ob[0];
    }
}

// ---------------- phase 7: GCN GEMM  s/f = relu(y @ W + b) ----------------
#define C_KC 25
__global__ __launch_bounds__(256) void k_gcn(
        const float* __restrict__ x,
        const float* __restrict__ Wsg, const float* __restrict__ bsg,
        const float* __restrict__ Wfg, const float* __restrict__ bfg, int n) {
    __shared__ __align__(16) float ys[C_KC][68];
    __shared__ __align__(16) float Wt[C_KC][260];
    __shared__ float sdis[64], sdinv[64];

    int part = blockIdx.y;
    const float* W    = part ? Wfg : Wsg;
    const float* bias = part ? bfg : bsg;
    int K    = part ? 200 : 100;
    int koff = part ? 100 : 0;
    int n0  = blockIdx.x * 64;
    int tid = threadIdx.x;

    if (tid < 64) {
        int nn = n0 + tid;
        sdis[tid]  = (nn < n) ? g_dis[nn]  : 0.f;
        sdinv[tid] = (nn < n) ? g_dinv[nn] : 0.f;
    }
    __syncthreads();

    int tm0 = (tid >> 5) * 8;
    int tn0 = (tid & 31) * 8;

    unsigned long long acc[8][4];
    #pragma unroll
    for (int r = 0; r < 8; r++)
        #pragma unroll
        for (int j = 0; j < 4; j++) acc[r][j] = 0ull;

    for (int kt = 0; kt < K; kt += C_KC) {
        for (int idx = tid; idx < 64 * C_KC; idx += 256) {
            int nn = idx / C_KC, kk = idx % C_KC;
            int node = n0 + nn;
            float v = 0.f;
            if (node < n) {
                int gk = koff + kt + kk;
                v = sdis[nn] * g_agg[node * FEAT + gk] + sdinv[nn] * x[node * FEAT + gk];
            }
            ys[kk][nn] = v;
        }
        #pragma unroll
        for (int it = 0; it < C_KC; it++)
            Wt[it][tid] = W[(kt + it) * 256 + tid];
        __syncthreads();

        #pragma unroll
        for (int kk = 0; kk < C_KC; kk++) {
            float4 a0 = *reinterpret_cast<const float4*>(&ys[kk][tm0]);
            float4 a1 = *reinterpret_cast<const float4*>(&ys[kk][tm0 + 4]);
            ulonglong2 w0 = *reinterpret_cast<const ulonglong2*>(&Wt[kk][tn0]);
            ulonglong2 w1 = *reinterpret_cast<const ulonglong2*>(&Wt[kk][tn0 + 4]);
            float av[8] = {a0.x, a0.y, a0.z, a0.w, a1.x, a1.y, a1.z, a1.w};
            #pragma unroll
            for (int r = 0; r < 8; r++) {
                unsigned long long ad = dup2(av[r]);
                fma2(acc[r][0], ad, w0.x);
                fma2(acc[r][1], ad, w0.y);
                fma2(acc[r][2], ad, w1.x);
                fma2(acc[r][3], ad, w1.y);
            }
        }
        __syncthreads();
    }

    float4 bv0 = *reinterpret_cast<const float4*>(&bias[tn0]);
    float4 bv1 = *reinterpret_cast<const float4*>(&bias[tn0 + 4]);
    #pragma unroll
    for (int r = 0; r < 8; r++) {
        int node = n0 + tm0 + r;
        if (node >= n) continue;
        float2 v0 = unpack2(acc[r][0]);
        float2 v1 = unpack2(acc[r][1]);
        float2 v2 = unpack2(acc[r][2]);
        float2 v3 = unpack2(acc[r][3]);
        float4 o0 = make_float4(fmaxf(v0.x + bv0.x, 0.f), fmaxf(v0.y + bv0.y, 0.f),
                                fmaxf(v1.x + bv0.z, 0.f), fmaxf(v1.y + bv0.w, 0.f));
        float4 o1 = make_float4(fmaxf(v2.x + bv1.x, 0.f), fmaxf(v2.y + bv1.y, 0.f),
                                fmaxf(v3.x + bv1.z, 0.f), fmaxf(v3.y + bv1.w, 0.f));
        float* dst = &g_sf[(size_t)node * 512 + part * 256 + tn0];
        *reinterpret_cast<float4*>(dst)     = o0;
        *reinterpret_cast<float4*>(dst + 4) = o1;
    }
}

// ---------------- phase 8: fused QK projection + attention, register-resident ----
// 32 nodes (64 tokens) per block. Each thread: 8 tokens x (8 Q-cols + 8 K-cols),
// Q col c and K col c live in the same thread (same head-dim) -> scores local.
// smem: As[256][68] + Bs[32][516] + dvS[512] + red[8]
#define D_SMEM_FLOATS (256*68 + 32*516 + 512 + 8)
extern __shared__ float dsm[];

__global__ __launch_bounds__(256, 1) void k_attn(
        const float* __restrict__ ipw, const float* __restrict__ ipb, int n) {
    float* As  = dsm;                 // [256][68] comb transposed: As[k][tok]
    float* Bs  = As + 256 * 68;       // [32][516] weight k-tile (Q rows 0:256, K rows 256:512)
    float* dvS = Bs + 32 * 516;       // [64][8]
    float* red = dvS + 512;

    int tid  = threadIdx.x;
    int n0   = blockIdx.x * 32;
    int warp = tid >> 5, lane = tid & 31;

    // load comb (s,f rows) transposed into As[k][tok], tok = local_node*2 + t
    #pragma unroll 4
    for (int i = 0; i < 64; i++) {
        int node = n0 + (i >> 1);
        float v = (node < n) ? g_sf[(size_t)node * 512 + (i & 1) * 256 + tid] : 0.f;
        As[tid * 68 + i] = v;
    }
    __syncthreads();

    // dv_{tok,h} = comb_tok . u_h + c_h  (h warp-uniform -> g_u reads broadcast)
    #pragma unroll
    for (int rep = 0; rep < 2; rep++) {
        int di = rep * 256 + tid;
        int h = di >> 6, tok = di & 63;
        float a = 0.f;
        #pragma unroll 8
        for (int k = 0; k < 256; k++) a += As[k * 68 + tok] * g_u[h * 256 + k];
        dvS[tok * 8 + h] = a + g_c[h];
    }

    int tm0 = warp * 8;        // token base (8 tokens = 4 nodes)
    int cq  = lane * 8;        // Q col base; K col = 256 + cq (same head-dims)

    unsigned long long aq[8][4], ak[8][4];
    #pragma unroll
    for (int r = 0; r < 8; r++)
        #pragma unroll
        for (int j = 0; j < 4; j++) { aq[r][j] = 0ull; ak[r][j] = 0ull; }

    for (int kt = 0; kt < 256; kt += 32) {
        // load Bs[kk][rr] for rr in [0,512): 16384 floats, 64/thread, coalesced
        __syncthreads();
        #pragma unroll
        for (int it = 0; it < 64; it++) {
            int idx = it * 256 + tid;
            int rr = idx >> 5, kk = idx & 31;
            Bs[kk * 516 + rr] = ipw[rr * 256 + kt + kk];
        }
        __syncthreads();
        #pragma unroll 8
        for (int kk = 0; kk < 32; kk++) {
            const float* as = &As[(kt + kk) * 68 + tm0];
            float4 a0 = *reinterpret_cast<const float4*>(as);        // broadcast
            float4 a1 = *reinterpret_cast<const float4*>(as + 4);
            const float* brow = &Bs[kk * 516];
            ulonglong2 bq0 = *reinterpret_cast<const ulonglong2*>(brow + cq);
            ulonglong2 bk0 = *reinterpret_cast<const ulonglong2*>(brow + 256 + cq);
            float av[8] = {a0.x, a0.y, a0.z, a0.w, a1.x, a1.y, a1.z, a1.w};
            #pragma unroll
            for (int r = 0; r < 8; r++) {
                unsigned long long ad = dup2(av[r]);
                fma2(aq[r][0], ad, bq0.x);
                fma2(aq[r][1], ad, bq0.y);
                fma2(ak[r][0], ad, bk0.x);
                fma2(ak[r][1], ad, bk0.y);
            }
            ulonglong2 bq1 = *reinterpret_cast<const ulonglong2*>(brow + cq + 4);
            ulonglong2 bk1 = *reinterpret_cast<const ulonglong2*>(brow + 260 + cq);
            #pragma unroll
            for (int r = 0; r < 8; r++) {
                unsigned long long ad = dup2(av[r]);
                fma2(aq[r][2], ad, bq1.x);
                fma2(aq[r][3], ad, bq1.y);
                fma2(ak[r][2], ad, bk1.x);
                fma2(ak[r][3], ad, bk1.y);
            }
        }
    }

    // unpack + bias
    float qf[8][8], kf[8][8];
    float bq[8], bk[8];
    *reinterpret_cast<float4*>(bq)     = *reinterpret_cast<const float4*>(&ipb[cq]);
    *reinterpret_cast<float4*>(bq + 4) = *reinterpret_cast<const float4*>(&ipb[cq + 4]);
    *reinterpret_cast<float4*>(bk)     = *reinterpret_cast<const float4*>(&ipb[256 + cq]);
    *reinterpret_cast<float4*>(bk + 4) = *reinterpret_cast<const float4*>(&ipb[260 + cq]);
    #pragma unroll
    for (int r = 0; r < 8; r++)
        #pragma unroll
        for (int j = 0; j < 4; j++) {
            float2 q2 = unpack2(aq[r][j]);
            float2 k2 = unpack2(ak[r][j]);
            qf[r][2 * j]     = q2.x + bq[2 * j];
            qf[r][2 * j + 1] = q2.y + bq[2 * j + 1];
            kf[r][2 * j]     = k2.x + bk[2 * j];
            kf[r][2 * j + 1] = k2.y + bk[2 * j + 1];
        }

    // per-node 2x2 scores; head h = lane>>2; reduce over 4-lane head group
    int h = lane >> 2;
    const float scale = 0.17677669529663687f;  // 1/sqrt(32)
    float csum = 0.f;
    #pragma unroll
    for (int m = 0; m < 4; m++) {
        int t0 = 2 * m, t1 = 2 * m + 1;
        float s00 = 0.f, s01 = 0.f, s10 = 0.f, s11 = 0.f;
        #pragma unroll
        for (int j = 0; j < 8; j++) {
            s00 += qf[t0][j] * kf[t0][j];
            s01 += qf[t0][j] * kf[t1][j];
            s10 += qf[t1][j] * kf[t0][j];
            s11 += qf[t1][j] * kf[t1][j];
        }
        #pragma unroll
        for (int off = 1; off <= 2; off <<= 1) {
            s00 += __shfl_xor_sync(0xffffffffu, s00, off);
            s01 += __shfl_xor_sync(0xffffffffu, s01, off);
            s10 += __shfl_xor_sync(0xffffffffu, s10, off);
            s11 += __shfl_xor_sync(0xffffffffu, s11, off);
        }
        s00 *= scale; s01 *= scale; s10 *= scale; s11 *= scale;
        float m0 = fmaxf(s00, s01), m1 = fmaxf(s10, s11);
        float e00 = expf(s00 - m0), e01 = expf(s01 - m0);
        float e10 = expf(s10 - m1), e11 = expf(s11 - m1);
        float d0 = e00 + e01, d1 = e10 + e11;
        float a00 = e00 / d0, a01 = e01 / d0;
        float a10 = e10 / d1, a11 = e11 / d1;
        int tokg = tm0 + t0;
        float dv0 = dvS[tokg * 8 + h];
        float dv1 = dvS[(tokg + 1) * 8 + h];
        float contrib = 0.125f * ((a00 + a10) * dv0 + (a01 + a11) * dv1); // 0.5 * 0.25 (4 dup lanes)
        int node = n0 + warp * 4 + m;
        if (node < n) csum += contrib;
    }

    // block reduce -> one atomic
    #pragma unroll
    for (int off = 16; off; off >>= 1)
        csum += __shfl_xor_sync(0xffffffffu, csum, off);
    if (lane == 0) red[warp] = csum;
    __syncthreads();
    if (tid == 0) {
        float s = 0.f;
        #pragma unroll
        for (int w = 0; w < 8; w++) s += red[w];
        atomicAdd(&g_acc[0], s);
    }
}

// ---------------- phase 9: final scalar ----------------
__global__ void k_final(float* __restrict__ out, int n) {
    out[0] = g_acc[0] / (float)n + g_konst[0];
}

// ---------------- launch ----------------
extern "C" void kernel_launch(void* const* d_in, const int* in_sizes, int n_in,
                              void* d_out, int out_size) {
    const float* x   = (const float*)d_in[0];
    const int*   ei  = (const int*)d_in[1];     // int32 (JAX x64 disabled)
    const float* W_s = (const float*)d_in[2];
    const float* b_s = (const float*)d_in[3];
    const float* W_f = (const float*)d_in[4];
    const float* b_f = (const float*)d_in[5];
    const float* ipw = (const float*)d_in[6];
    const float* ipb = (const float*)d_in[7];
    const float* opw = (const float*)d_in[8];
    const float* opb = (const float*)d_in[9];
    const float* ow  = (const float*)d_in[10];
    const float* ob  = (const float*)d_in[11];

    int n = in_sizes[0] / FEAT;
    int E = in_sizes[1] / 2;
    int nb = (n + 255) / 256;

    k_zero<<<(n + 255) / 256, 256>>>(n);
    k_deg<<<(E + 255) / 256, 256>>>(ei, E);
    k_dis<<<(n + 255) / 256, 256>>>(n);
    k_scanA<<<nb, 256>>>(n);
    k_scanB<<<1, 256>>>(nb, n);
    k_scanC<<<nb, 256>>>(n);
    k_scatter<<<(E + 255) / 256, 256>>>(ei, E);
    k_gather<<<(n + 7) / 8, 256>>>(x, n);
    k_prep<<<1, 256>>>(ipw, ipb, opw, opb, ow, ob);

    dim3 gc((n + 63) / 64, 2);
    k_gcn<<<gc, 256>>>(x, W_s, b_s, W_f, b_f, n);

    int dsm_bytes = D_SMEM_FLOATS * 4;
    cudaFuncSetAttribute(k_attn, cudaFuncAttributeMaxDynamicSharedMemorySize, dsm_bytes);
    k_attn<<<(n + 31) / 32, 256, dsm_bytes>>>(ipw, ipb, n);

    k_final<<<1, 1>>>((float*)d_out, n);
}

// round 6
// speedup vs baseline: 2.3927x; 1.8719x over previous
#include <cuda_runtime.h>
#include <cuda_bf16.h>
#include <cstdint>

#define N_NODES_MAX 50000
#define E_MAX 1600000
#define FEAT 300
#define HID 256

// ---------------- device scratch (no allocations allowed) ----------------
__device__ int   g_degi[N_NODES_MAX];
__device__ int   g_off [N_NODES_MAX + 1];
__device__ int   g_cur [N_NODES_MAX];
__device__ int   g_srcs[E_MAX];
__device__ int   g_bsum[256];
__device__ int   g_bpre[256];
__device__ __align__(16) float g_dis [N_NODES_MAX];
__device__ __align__(16) float g_dinv[N_NODES_MAX];
__device__ __align__(16) float g_agg [N_NODES_MAX * FEAT];
__device__ __align__(16) __nv_bfloat16 g_sfb[N_NODES_MAX * 2 * HID]; // comb bf16
__device__ __align__(16) __nv_bfloat16 g_wb [512 * 256];             // QK weights bf16
__device__ __align__(16) float g_u   [8 * 256];
__device__ __align__(16) float g_c   [8];
__device__ float g_konst[1];
__device__ float g_acc [1];

// ---------------- f32x2 helpers ----------------
__device__ __forceinline__ void fma2(unsigned long long &d,
                                     unsigned long long a,
                                     unsigned long long b) {
    asm("fma.rn.f32x2 %0, %1, %2, %0;" : "+l"(d) : "l"(a), "l"(b));
}
__device__ __forceinline__ unsigned long long dup2(float x) {
    unsigned long long r;
    asm("mov.b64 %0, {%1, %1};" : "=l"(r) : "f"(x));
    return r;
}
__device__ __forceinline__ float2 unpack2(unsigned long long v) {
    float2 r;
    asm("mov.b64 {%0, %1}, %2;" : "=f"(r.x), "=f"(r.y) : "l"(v));
    return r;
}

// ---------------- mma.sync helpers (base ISA, works on sm_103) ----------------
__device__ __forceinline__ uint32_t smem_u32(const void* p) {
    uint32_t a;
    asm("{ .reg .u64 t; cvta.to.shared.u64 t, %1; cvt.u32.u64 %0, t; }"
        : "=r"(a) : "l"(p));
    return a;
}
__device__ __forceinline__ void ldsm4(uint32_t& r0, uint32_t& r1,
                                      uint32_t& r2, uint32_t& r3, uint32_t addr) {
    asm volatile("ldmatrix.sync.aligned.m8n8.x4.shared.b16 {%0,%1,%2,%3}, [%4];"
                 : "=r"(r0), "=r"(r1), "=r"(r2), "=r"(r3) : "r"(addr));
}
__device__ __forceinline__ void mma16816(float* d, const uint32_t* a,
                                         uint32_t b0, uint32_t b1) {
    asm volatile(
        "mma.sync.aligned.m16n8k16.row.col.f32.bf16.bf16.f32 "
        "{%0,%1,%2,%3}, {%4,%5,%6,%7}, {%8,%9}, {%0,%1,%2,%3};"
        : "+f"(d[0]), "+f"(d[1]), "+f"(d[2]), "+f"(d[3])
        : "r"(a[0]), "r"(a[1]), "r"(a[2]), "r"(a[3]), "r"(b0), "r"(b1));
}

// ---------------- phases 0-4: degree, CSR ----------------
__global__ void k_zero(int n) {
    int i = blockIdx.x * blockDim.x + threadIdx.x;
    if (i < n) g_degi[i] = 0;
    if (i == 0) g_acc[0] = 0.f;
}
__global__ void k_deg(const int* __restrict__ ei, int E) {
    int i = blockIdx.x * blockDim.x + threadIdx.x;
    if (i < E) atomicAdd(&g_degi[ei[E + i]], 1);
}
__global__ void k_dis(int n) {
    int i = blockIdx.x * blockDim.x + threadIdx.x;
    if (i < n) {
        float d = 1.0f + (float)g_degi[i];
        g_dis[i]  = rsqrtf(d);
        g_dinv[i] = 1.0f / d;
    }
}
__global__ void k_scanA(int n) {
    __shared__ int sh[8];
    int i = blockIdx.x * 256 + threadIdx.x;
    int v = (i < n) ? g_degi[i] : 0;
    #pragma unroll
    for (int off = 16; off; off >>= 1) v += __shfl_xor_sync(0xffffffffu, v, off);
    if ((threadIdx.x & 31) == 0) sh[threadIdx.x >> 5] = v;
    __syncthreads();
    if (threadIdx.x == 0) {
        int s = 0;
        #pragma unroll
        for (int w = 0; w < 8; w++) s += sh[w];
        g_bsum[blockIdx.x] = s;
    }
}
__global__ void k_scanB(int nb, int n) {
    __shared__ int sh[256];
    int t = threadIdx.x;
    int v = (t < nb) ? g_bsum[t] : 0;
    sh[t] = v;
    __syncthreads();
    #pragma unroll
    for (int off = 1; off < 256; off <<= 1) {
        int u = (t >= off) ? sh[t - off] : 0;
        __syncthreads();
        sh[t] += u;
        __syncthreads();
    }
    if (t < nb) g_bpre[t] = sh[t] - v;
    if (t == nb - 1) g_off[n] = sh[t];
}
__global__ void k_scanC(int n) {
    __shared__ int sh[256];
    int t = threadIdx.x;
    int i = blockIdx.x * 256 + t;
    int v = (i < n) ? g_degi[i] : 0;
    sh[t] = v;
    __syncthreads();
    #pragma unroll
    for (int off = 1; off < 256; off <<= 1) {
        int u = (t >= off) ? sh[t - off] : 0;
        __syncthreads();
        sh[t] += u;
        __syncthreads();
    }
    if (i < n) {
        int off = g_bpre[blockIdx.x] + sh[t] - v;
        g_off[i] = off;
        g_cur[i] = off;
    }
}
__global__ void k_scatter(const int* __restrict__ ei, int E) {
    int i = blockIdx.x * blockDim.x + threadIdx.x;
    if (i >= E) return;
    int s = ei[i];
    int d = ei[E + i];
    int pos = atomicAdd(&g_cur[d], 1);
    g_srcs[pos] = s;
}

// ---------------- phase 5: gather-aggregate ----------------
__global__ __launch_bounds__(256) void k_gather(const float* __restrict__ x, int n) {
    int w    = (blockIdx.x * blockDim.x + threadIdx.x) >> 5;
    int lane = threadIdx.x & 31;
    if (w >= n) return;
    int beg = g_off[w], end = g_off[w + 1];

    float4 a0 = make_float4(0.f, 0.f, 0.f, 0.f);
    float4 a1 = a0, a2 = a0;

    for (int base = beg; base < end; base += 32) {
        int cnt = min(32, end - base);
        int   s_l = 0;
        float w_l = 0.f;
        if (lane < cnt) {
            s_l = g_srcs[base + lane];
            w_l = g_dis[s_l];
        }
        if (cnt == 32) {
            #pragma unroll 4
            for (int k = 0; k < 32; k++) {
                int   s  = __shfl_sync(0xffffffffu, s_l, k);
                float wt = __shfl_sync(0xffffffffu, w_l, k);
                const float4* xr = reinterpret_cast<const float4*>(x + (size_t)s * FEAT);
                float4 v0 = __ldg(&xr[lane]);
                float4 v1 = __ldg(&xr[lane + 32]);
                a0.x += wt * v0.x; a0.y += wt * v0.y; a0.z += wt * v0.z; a0.w += wt * v0.w;
                a1.x += wt * v1.x; a1.y += wt * v1.y; a1.z += wt * v1.z; a1.w += wt * v1.w;
                if (lane < 11) {
                    float4 v2 = __ldg(&xr[lane + 64]);
                    a2.x += wt * v2.x; a2.y += wt * v2.y; a2.z += wt * v2.z; a2.w += wt * v2.w;
                }
            }
        } else {
            for (int k = 0; k < cnt; k++) {
                int   s  = __shfl_sync(0xffffffffu, s_l, k);
                float wt = __shfl_sync(0xffffffffu, w_l, k);
                const float4* xr = reinterpret_cast<const float4*>(x + (size_t)s * FEAT);
                float4 v0 = __ldg(&xr[lane]);
                float4 v1 = __ldg(&xr[lane + 32]);
                a0.x += wt * v0.x; a0.y += wt * v0.y; a0.z += wt * v0.z; a0.w += wt * v0.w;
                a1.x += wt * v1.x; a1.y += wt * v1.y; a1.z += wt * v1.z; a1.w += wt * v1.w;
                if (lane < 11) {
                    float4 v2 = __ldg(&xr[lane + 64]);
                    a2.x += wt * v2.x; a2.y += wt * v2.y; a2.z += wt * v2.z; a2.w += wt * v2.w;
                }
            }
        }
    }
    float4* ar = reinterpret_cast<float4*>(g_agg + (size_t)w * FEAT);
    ar[lane]      = a0;
    ar[lane + 32] = a1;
    if (lane < 11) ar[lane + 64] = a2;
}

// ---------------- phase 6: fold weights + convert QK weights to bf16 ----------
__global__ void k_prep(const float* __restrict__ ipw, const float* __restrict__ ipb,
                       const float* __restrict__ opw, const float* __restrict__ opb,
                       const float* __restrict__ ow,  const float* __restrict__ ob) {
    __shared__ float vout[256];
    int t = threadIdx.x;
    float acc = 0.f;
    for (int j = 0; j < 256; j++) acc += opw[j * 256 + t] * ow[j];
    vout[t] = acc;
    __syncthreads();
    #pragma unroll
    for (int h = 0; h < 8; h++) {
        float a = 0.f;
        #pragma unroll 8
        for (int d = 0; d < 32; d++)
            a += ipw[(512 + h * 32 + d) * 256 + t] * vout[h * 32 + d];
        g_u[h * 256 + t] = a;
    }
    if (t < 8) {
        float c = 0.f;
        for (int d = 0; d < 32; d++) c += ipb[512 + t * 32 + d] * vout[t * 32 + d];
        g_c[t] = c;
    }
    if (t == 0) {
        float c = 0.f;
        for (int j = 0; j < 256; j++) c += opb[j] * ow[j];
        g_konst[0] = c + ob[0];
    }
}
__global__ void k_wconv(const float* __restrict__ ipw) {
    int i = blockIdx.x * 256 + threadIdx.x;
    if (i < 512 * 256 / 2) {
        float2 f = reinterpret_cast<const float2*>(ipw)[i];
        reinterpret_cast<__nv_bfloat162*>(g_wb)[i] = __float22bfloat162_rn(f);
    }
}

// ---------------- phase 7: GCN GEMM -> bf16 comb ----------------
#define C_KC 25
__global__ __launch_bounds__(256) void k_gcn(
        const float* __restrict__ x,
        const float* __restrict__ Wsg, const float* __restrict__ bsg,
        const float* __restrict__ Wfg, const float* __restrict__ bfg, int n) {
    __shared__ __align__(16) float ys[C_KC][68];
    __shared__ __align__(16) float Wt[C_KC][260];
    __shared__ float sdis[64], sdinv[64];

    int part = blockIdx.y;
    const float* W    = part ? Wfg : Wsg;
    const float* bias = part ? bfg : bsg;
    int K    = part ? 200 : 100;
    int koff = part ? 100 : 0;
    int n0  = blockIdx.x * 64;
    int tid = threadIdx.x;

    if (tid < 64) {
        int nn = n0 + tid;
        sdis[tid]  = (nn < n) ? g_dis[nn]  : 0.f;
        sdinv[tid] = (nn < n) ? g_dinv[nn] : 0.f;
    }
    __syncthreads();

    int tm0 = (tid >> 5) * 8;
    int tn0 = (tid & 31) * 8;

    unsigned long long acc[8][4];
    #pragma unroll
    for (int r = 0; r < 8; r++)
        #pragma unroll
        for (int j = 0; j < 4; j++) acc[r][j] = 0ull;

    for (int kt = 0; kt < K; kt += C_KC) {
        for (int idx = tid; idx < 64 * C_KC; idx += 256) {
            int nn = idx / C_KC, kk = idx % C_KC;
            int node = n0 + nn;
            float v = 0.f;
            if (node < n) {
                int gk = koff + kt + kk;
                v = sdis[nn] * g_agg[node * FEAT + gk] + sdinv[nn] * x[node * FEAT + gk];
            }
            ys[kk][nn] = v;
        }
        #pragma unroll
        for (int it = 0; it < C_KC; it++)
            Wt[it][tid] = W[(kt + it) * 256 + tid];
        __syncthreads();

        #pragma unroll
        for (int kk = 0; kk < C_KC; kk++) {
            float4 a0 = *reinterpret_cast<const float4*>(&ys[kk][tm0]);
            float4 a1 = *reinterpret_cast<const float4*>(&ys[kk][tm0 + 4]);
            ulonglong2 w0 = *reinterpret_cast<const ulonglong2*>(&Wt[kk][tn0]);
            ulonglong2 w1 = *reinterpret_cast<const ulonglong2*>(&Wt[kk][tn0 + 4]);
            float av[8] = {a0.x, a0.y, a0.z, a0.w, a1.x, a1.y, a1.z, a1.w};
            #pragma unroll
            for (int r = 0; r < 8; r++) {
                unsigned long long ad = dup2(av[r]);
                fma2(acc[r][0], ad, w0.x);
                fma2(acc[r][1], ad, w0.y);
                fma2(acc[r][2], ad, w1.x);
                fma2(acc[r][3], ad, w1.y);
            }
        }
        __syncthreads();
    }

    float4 bv0 = *reinterpret_cast<const float4*>(&bias[tn0]);
    float4 bv1 = *reinterpret_cast<const float4*>(&bias[tn0 + 4]);
    #pragma unroll
    for (int r = 0; r < 8; r++) {
        int node = n0 + tm0 + r;
        if (node >= n) continue;
        float2 v0 = unpack2(acc[r][0]);
        float2 v1 = unpack2(acc[r][1]);
        float2 v2 = unpack2(acc[r][2]);
        float2 v3 = unpack2(acc[r][3]);
        __nv_bfloat162 p0 = __float22bfloat162_rn(
            make_float2(fmaxf(v0.x + bv0.x, 0.f), fmaxf(v0.y + bv0.y, 0.f)));
        __nv_bfloat162 p1 = __float22bfloat162_rn(
            make_float2(fmaxf(v1.x + bv0.z, 0.f), fmaxf(v1.y + bv0.w, 0.f)));
        __nv_bfloat162 p2 = __float22bfloat162_rn(
            make_float2(fmaxf(v2.x + bv1.x, 0.f), fmaxf(v2.y + bv1.y, 0.f)));
        __nv_bfloat162 p3 = __float22bfloat162_rn(
            make_float2(fmaxf(v3.x + bv1.z, 0.f), fmaxf(v3.y + bv1.w, 0.f)));
        uint4 st;
        st.x = *reinterpret_cast<unsigned*>(&p0);
        st.y = *reinterpret_cast<unsigned*>(&p1);
        st.z = *reinterpret_cast<unsigned*>(&p2);
        st.w = *reinterpret_cast<unsigned*>(&p3);
        *reinterpret_cast<uint4*>(&g_sfb[(size_t)node * 512 + part * 256 + tn0]) = st;
    }
}

// ---------------- phase 8: HMMA (mma.sync bf16) QK projection + attention ----
// 32 nodes = 64 tokens per block. Q = cols 0:256 of D, K = cols 256:512.
// A smem: 64 tok x 264 bf16 (pad) ; B smem: 512 n x 72 bf16 (pad), k-chunk 64
// Out (fp32 64x520) unioned over B region after mainloop.
#define AT_PAD 264
#define BT_PAD 72
#define SM_A    0
#define SM_BO   33792                       // max(B 73728, Out 133120)
#define SM_US   (SM_BO + 133120)            // 8192
#define SM_DV   (SM_US + 8192)              // 2048  (64 tok x 8 h)
#define SM_BIAS (SM_DV + 2048)              // 2048
#define SM_RED  (SM_BIAS + 2048)            // 32
#define SM_TOTAL (SM_RED + 32)

__global__ __launch_bounds__(256, 1) void k_attn(
        const float* __restrict__ ipb, int n) {
    extern __shared__ __align__(1024) unsigned char smraw[];
    __nv_bfloat16* A  = reinterpret_cast<__nv_bfloat16*>(smraw + SM_A);
    __nv_bfloat16* B  = reinterpret_cast<__nv_bfloat16*>(smraw + SM_BO);
    float* Out   = reinterpret_cast<float*>(smraw + SM_BO);
    float* us    = reinterpret_cast<float*>(smraw + SM_US);
    float* dvS   = reinterpret_cast<float*>(smraw + SM_DV);
    float* sbias = reinterpret_cast<float*>(smraw + SM_BIAS);
    float* red   = reinterpret_cast<float*>(smraw + SM_RED);

    int tid = threadIdx.x, wid = tid >> 5, lane = tid & 31;
    int n0 = blockIdx.x * 32;

    // stage u transposed [k][8] and bias
    for (int i = tid; i < 2048; i += 256) {
        int h = i >> 8, k = i & 255;
        us[k * 8 + h] = g_u[i];
    }
    for (int i = tid; i < 512; i += 256) sbias[i] = ipb[i];

    // load A: 64 tokens x 256 k bf16 (4 bf16 = one u64 per chunk)
    #pragma unroll
    for (int it = 0; it < 16; it++) {
        int i = it * 256 + tid;
        int tok = i >> 6, k4 = i & 63;
        int node = n0 + (tok >> 1);
        unsigned long long v = 0ull;
        if (node < n)
            v = *reinterpret_cast<const unsigned long long*>(
                    &g_sfb[(size_t)node * 512 + (tok & 1) * 256 + k4 * 4]);
        *reinterpret_cast<unsigned long long*>(&A[tok * AT_PAD + k4 * 4]) = v;
    }

    uint32_t a_base = smem_u32(A);
    uint32_t b_base = smem_u32(B);

    int mt = wid & 3;        // m-tile (16 tokens)
    int nh = wid >> 2;       // n-half (256 cols)

    float acc[32][4];
    #pragma unroll
    for (int j = 0; j < 32; j++)
        #pragma unroll
        for (int r = 0; r < 4; r++) acc[j][r] = 0.f;

    // precomputed ldmatrix lane addressing
    int a_row = mt * 16 + (lane & 15);
    int a_col8 = (lane >> 4) * 8;
    int b_rofs = (lane & 7) + (lane >> 4) * 8;   // within 16-row ntile pair
    int b_col8 = ((lane >> 3) & 1) * 8;

    for (int c = 0; c < 4; c++) {
        __syncthreads();
        // load B chunk c: 512 rows x 64 k bf16
        #pragma unroll
        for (int it = 0; it < 32; it++) {
            int i = it * 256 + tid;
            int rr = i >> 4, k4 = i & 15;
            unsigned long long v = *reinterpret_cast<const unsigned long long*>(
                &g_wb[rr * 256 + c * 64 + k4 * 4]);
            *reinterpret_cast<unsigned long long*>(&B[rr * BT_PAD + k4 * 4]) = v;
        }
        __syncthreads();

        #pragma unroll
        for (int ks = 0; ks < 4; ks++) {
            uint32_t af[4];
            uint32_t aaddr = a_base +
                (uint32_t)(a_row * AT_PAD + c * 64 + ks * 16 + a_col8) * 2;
            ldsm4(af[0], af[1], af[2], af[3], aaddr);
            #pragma unroll
            for (int j = 0; j < 16; j++) {
                int nrow = nh * 256 + j * 16 + b_rofs;
                uint32_t baddr = b_base +
                    (uint32_t)(nrow * BT_PAD + ks * 16 + b_col8) * 2;
                uint32_t b0, b1, b2, b3;
                ldsm4(b0, b1, b2, b3, baddr);
                mma16816(acc[2 * j],     af, b0, b1);
                mma16816(acc[2 * j + 1], af, b2, b3);
            }
        }
    }
    __syncthreads();   // B reads done -> Out may overwrite region

    // write D + bias to Out [64][520]
    {
        int row0 = mt * 16 + (lane >> 2);
        int cofs = (lane & 3) * 2;
        #pragma unroll
        for (int j = 0; j < 32; j++) {
            int col = nh * 256 + j * 8 + cofs;
            float bb0 = sbias[col], bb1 = sbias[col + 1];
            Out[row0 * 520 + col]           = acc[j][0] + bb0;
            Out[row0 * 520 + col + 1]       = acc[j][1] + bb1;
            Out[(row0 + 8) * 520 + col]     = acc[j][2] + bb0;
            Out[(row0 + 8) * 520 + col + 1] = acc[j][3] + bb1;
        }
    }

    // dv_{tok,h} = comb_tok . u_h + c_h  (512 dots, 2 per thread)
    #pragma unroll
    for (int rep = 0; rep < 2; rep++) {
        int di = rep * 256 + tid;
        int tok = di >> 3, h = di & 7;
        const __nv_bfloat16* ar = &A[tok * AT_PAD];
        float a = 0.f;
        #pragma unroll 4
        for (int k = 0; k < 256; k += 2) {
            float2 f = __bfloat1622float2(
                *reinterpret_cast<const __nv_bfloat162*>(&ar[k]));
            a += f.x * us[k * 8 + h] + f.y * us[(k + 1) * 8 + h];
        }
        dvS[tok * 8 + h] = a + g_c[h];
    }
    __syncthreads();

    // per (node, head) 2x2 attention  (round-3 proven epilogue)
    int node = tid >> 3, h = tid & 7;
    const float* q0 = &Out[(node * 2 + 0) * 520 + h * 32];
    const float* q1 = &Out[(node * 2 + 1) * 520 + h * 32];
    const float* k0 = &Out[(node * 2 + 0) * 520 + 256 + h * 32];
    const float* k1 = &Out[(node * 2 + 1) * 520 + 256 + h * 32];
    float s00 = 0.f, s01 = 0.f, s10 = 0.f, s11 = 0.f;
    #pragma unroll
    for (int d = 0; d < 32; d++) {
        float a0 = q0[d], a1 = q1[d], b0 = k0[d], b1 = k1[d];
        s00 += a0 * b0; s01 += a0 * b1; s10 += a1 * b0; s11 += a1 * b1;
    }
    const float scale = 0.17677669529663687f;  // 1/sqrt(32)
    s00 *= scale; s01 *= scale; s10 *= scale; s11 *= scale;
    float m0 = fmaxf(s00, s01), m1 = fmaxf(s10, s11);
    float e00 = expf(s00 - m0), e01 = expf(s01 - m0);
    float e10 = expf(s10 - m1), e11 = expf(s11 - m1);
    float d0 = e00 + e01, d1 = e10 + e11;
    float a00 = e00 / d0, a01 = e01 / d0;
    float a10 = e10 / d1, a11 = e11 / d1;
    float dv0 = dvS[(node * 2) * 8 + h];
    float dv1 = dvS[(node * 2 + 1) * 8 + h];
    float contrib = 0.5f * ((a00 + a10) * dv0 + (a01 + a11) * dv1);
    if (n0 + node >= n) contrib = 0.f;

    #pragma unroll
    for (int off = 16; off; off >>= 1)
        contrib += __shfl_xor_sync(0xffffffffu, contrib, off);
    if (lane == 0) red[wid] = contrib;
    __syncthreads();
    if (tid == 0) {
        float s = 0.f;
        #pragma unroll
        for (int w = 0; w < 8; w++) s += red[w];
        atomicAdd(&g_acc[0], s);
    }
}

// ---------------- phase 9: final scalar ----------------
__global__ void k_final(float* __restrict__ out, int n) {
    out[0] = g_acc[0] / (float)n + g_konst[0];
}

// ---------------- launch ----------------
extern "C" void kernel_launch(void* const* d_in, const int* in_sizes, int n_in,
                              void* d_out, int out_size) {
    const float* x   = (const float*)d_in[0];
    const int*   ei  = (const int*)d_in[1];
    const float* W_s = (const float*)d_in[2];
    const float* b_s = (const float*)d_in[3];
    const float* W_f = (const float*)d_in[4];
    const float* b_f = (const float*)d_in[5];
    const float* ipw = (const float*)d_in[6];
    const float* ipb = (const float*)d_in[7];
    const float* opw = (const float*)d_in[8];
    const float* opb = (const float*)d_in[9];
    const float* ow  = (const float*)d_in[10];
    const float* ob  = (const float*)d_in[11];

    int n = in_sizes[0] / FEAT;
    int E = in_sizes[1] / 2;
    int nb = (n + 255) / 256;

    k_zero<<<(n + 255) / 256, 256>>>(n);
    k_deg<<<(E + 255) / 256, 256>>>(ei, E);
    k_dis<<<(n + 255) / 256, 256>>>(n);
    k_scanA<<<nb, 256>>>(n);
    k_scanB<<<1, 256>>>(nb, n);
    k_scanC<<<nb, 256>>>(n);
    k_scatter<<<(E + 255) / 256, 256>>>(ei, E);
    k_gather<<<(n + 7) / 8, 256>>>(x, n);
    k_prep<<<1, 256>>>(ipw, ipb, opw, opb, ow, ob);
    k_wconv<<<256, 256>>>(ipw);

    dim3 gc((n + 63) / 64, 2);
    k_gcn<<<gc, 256>>>(x, W_s, b_s, W_f, b_f, n);

    cudaFuncSetAttribute(k_attn, cudaFuncAttributeMaxDynamicSharedMemorySize, SM_TOTAL);
    k_attn<<<(n + 31) / 32, 256, SM_TOTAL>>>(ipb, n);

    k_final<<<1, 1>>>((float*)d_out, n);
}

// round 7
// speedup vs baseline: 3.1245x; 1.3059x over previous
#include <cuda_runtime.h>
#include <cuda_bf16.h>
#include <cstdint>

#define N_NODES_MAX 50000
#define E_MAX 1600000
#define FEAT 300
#define XB_PAD 304              // padded bf16 row (38 uint4)
#define HID 256

// ---------------- device scratch ----------------
__device__ int   g_degi[N_NODES_MAX];
__device__ int   g_off [N_NODES_MAX + 1];
__device__ int   g_cur [N_NODES_MAX];
__device__ int   g_srcs[E_MAX];
__device__ int   g_bsum[256];
__device__ int   g_bpre[256];
__device__ __align__(16) float g_dis [N_NODES_MAX];
__device__ __align__(16) float g_dinv[N_NODES_MAX];
__device__ __align__(16) __nv_bfloat16 g_xb [N_NODES_MAX * XB_PAD];  // x bf16 padded
__device__ __align__(16) __nv_bfloat16 g_yb [N_NODES_MAX * XB_PAD];  // y = dis*agg+dinv*x
__device__ __align__(16) __nv_bfloat16 g_sfb[N_NODES_MAX * 2 * HID]; // comb bf16
__device__ __align__(16) __nv_bfloat16 g_wb [512 * 256];             // QK weights bf16
__device__ __align__(16) __nv_bfloat16 g_wg [512 * 320];             // block-diag GCN W bf16
__device__ __align__(16) float g_u   [8 * 256];
__device__ __align__(16) float g_c   [8];
__device__ float g_konst[1];
__device__ float g_acc [1];

// ---------------- helpers ----------------
__device__ __forceinline__ float2 bf2_to_f2(uint32_t u) {
    float2 r;
    r.x = __uint_as_float(u << 16);
    r.y = __uint_as_float(u & 0xffff0000u);
    return r;
}
__device__ __forceinline__ uint32_t f2_to_bf2(float a, float b) {
    __nv_bfloat162 p = __float22bfloat162_rn(make_float2(a, b));
    return *reinterpret_cast<uint32_t*>(&p);
}
__device__ __forceinline__ uint32_t smem_u32(const void* p) {
    uint32_t a;
    asm("{ .reg .u64 t; cvta.to.shared.u64 t, %1; cvt.u32.u64 %0, t; }"
        : "=r"(a) : "l"(p));
    return a;
}
__device__ __forceinline__ void ldsm4(uint32_t& r0, uint32_t& r1,
                                      uint32_t& r2, uint32_t& r3, uint32_t addr) {
    asm volatile("ldmatrix.sync.aligned.m8n8.x4.shared.b16 {%0,%1,%2,%3}, [%4];"
                 : "=r"(r0), "=r"(r1), "=r"(r2), "=r"(r3) : "r"(addr));
}
__device__ __forceinline__ void mma16816(float* d, const uint32_t* a,
                                         uint32_t b0, uint32_t b1) {
    asm volatile(
        "mma.sync.aligned.m16n8k16.row.col.f32.bf16.bf16.f32 "
        "{%0,%1,%2,%3}, {%4,%5,%6,%7}, {%8,%9}, {%0,%1,%2,%3};"
        : "+f"(d[0]), "+f"(d[1]), "+f"(d[2]), "+f"(d[3])
        : "r"(a[0]), "r"(a[1]), "r"(a[2]), "r"(a[3]), "r"(b0), "r"(b1));
}

// ---------------- phases 0-4: degree, CSR ----------------
__global__ void k_zero(int n) {
    int i = blockIdx.x * blockDim.x + threadIdx.x;
    if (i < n) g_degi[i] = 0;
    if (i == 0) g_acc[0] = 0.f;
}
__global__ void k_deg(const int* __restrict__ ei, int E) {
    int i = blockIdx.x * blockDim.x + threadIdx.x;
    if (i < E) atomicAdd(&g_degi[ei[E + i]], 1);
}
__global__ void k_dis(int n) {
    int i = blockIdx.x * blockDim.x + threadIdx.x;
    if (i < n) {
        float d = 1.0f + (float)g_degi[i];
        g_dis[i]  = rsqrtf(d);
        g_dinv[i] = 1.0f / d;
    }
}
__global__ void k_scanA(int n) {
    __shared__ int sh[8];
    int i = blockIdx.x * 256 + threadIdx.x;
    int v = (i < n) ? g_degi[i] : 0;
    #pragma unroll
    for (int off = 16; off; off >>= 1) v += __shfl_xor_sync(0xffffffffu, v, off);
    if ((threadIdx.x & 31) == 0) sh[threadIdx.x >> 5] = v;
    __syncthreads();
    if (threadIdx.x == 0) {
        int s = 0;
        #pragma unroll
        for (int w = 0; w < 8; w++) s += sh[w];
        g_bsum[blockIdx.x] = s;
    }
}
__global__ void k_scanB(int nb, int n) {
    __shared__ int sh[256];
    int t = threadIdx.x;
    int v = (t < nb) ? g_bsum[t] : 0;
    sh[t] = v;
    __syncthreads();
    #pragma unroll
    for (int off = 1; off < 256; off <<= 1) {
        int u = (t >= off) ? sh[t - off] : 0;
        __syncthreads();
        sh[t] += u;
        __syncthreads();
    }
    if (t < nb) g_bpre[t] = sh[t] - v;
    if (t == nb - 1) g_off[n] = sh[t];
}
__global__ void k_scanC(int n) {
    __shared__ int sh[256];
    int t = threadIdx.x;
    int i = blockIdx.x * 256 + t;
    int v = (i < n) ? g_degi[i] : 0;
    sh[t] = v;
    __syncthreads();
    #pragma unroll
    for (int off = 1; off < 256; off <<= 1) {
        int u = (t >= off) ? sh[t - off] : 0;
        __syncthreads();
        sh[t] += u;
        __syncthreads();
    }
    if (i < n) {
        int off = g_bpre[blockIdx.x] + sh[t] - v;
        g_off[i] = off;
        g_cur[i] = off;
    }
}
__global__ void k_scatter(const int* __restrict__ ei, int E) {
    int i = blockIdx.x * blockDim.x + threadIdx.x;
    if (i >= E) return;
    int s = ei[i];
    int d = ei[E + i];
    int pos = atomicAdd(&g_cur[d], 1);
    g_srcs[pos] = s;
}

// ---------------- phase 5a: x -> bf16 padded ----------------
__global__ void k_xconv(const float* __restrict__ x, int n) {
    int i = blockIdx.x * 256 + threadIdx.x;   // over n*152 bf162 pairs
    if (i >= n * 152) return;
    int row = i / 152, p = i % 152;
    uint32_t v = 0;
    if (p < 150) {
        float2 f = *reinterpret_cast<const float2*>(&x[row * FEAT + 2 * p]);
        v = f2_to_bf2(f.x, f.y);
    }
    *reinterpret_cast<uint32_t*>(&g_xb[row * XB_PAD + 2 * p]) = v;
}

// ---------------- phase 5b: gather-aggregate (bf16 reads) + y epilogue --------
__global__ __launch_bounds__(256) void k_gather(int n) {
    int w    = (blockIdx.x * blockDim.x + threadIdx.x) >> 5;
    int lane = threadIdx.x & 31;
    if (w >= n) return;
    int beg = g_off[w], end = g_off[w + 1];

    float acc0[8], acc1[8];
    #pragma unroll
    for (int j = 0; j < 8; j++) { acc0[j] = 0.f; acc1[j] = 0.f; }

    for (int base = beg; base < end; base += 32) {
        int cnt = min(32, end - base);
        int   s_l = 0;
        float w_l = 0.f;
        if (lane < cnt) {
            s_l = g_srcs[base + lane];
            w_l = g_dis[s_l];
        }
        for (int k = 0; k < cnt; k++) {
            int   s  = __shfl_sync(0xffffffffu, s_l, k);
            float wt = __shfl_sync(0xffffffffu, w_l, k);
            const uint4* xr = reinterpret_cast<const uint4*>(g_xb + (size_t)s * XB_PAD);
            uint4 v = __ldg(&xr[lane]);
            float2 f;
            f = bf2_to_f2(v.x); acc0[0] += wt * f.x; acc0[1] += wt * f.y;
            f = bf2_to_f2(v.y); acc0[2] += wt * f.x; acc0[3] += wt * f.y;
            f = bf2_to_f2(v.z); acc0[4] += wt * f.x; acc0[5] += wt * f.y;
            f = bf2_to_f2(v.w); acc0[6] += wt * f.x; acc0[7] += wt * f.y;
            if (lane < 6) {
                uint4 v2 = __ldg(&xr[32 + lane]);
                f = bf2_to_f2(v2.x); acc1[0] += wt * f.x; acc1[1] += wt * f.y;
                f = bf2_to_f2(v2.y); acc1[2] += wt * f.x; acc1[3] += wt * f.y;
                f = bf2_to_f2(v2.z); acc1[4] += wt * f.x; acc1[5] += wt * f.y;
                f = bf2_to_f2(v2.w); acc1[6] += wt * f.x; acc1[7] += wt * f.y;
            }
        }
    }

    // y = dis*agg + dinv*x_self  -> bf16
    float dw = g_dis[w], iw = g_dinv[w];
    const uint4* xr = reinterpret_cast<const uint4*>(g_xb + (size_t)w * XB_PAD);
    uint4* yr = reinterpret_cast<uint4*>(g_yb + (size_t)w * XB_PAD);
    {
        uint4 xs = xr[lane];
        float2 f0 = bf2_to_f2(xs.x), f1 = bf2_to_f2(xs.y);
        float2 f2 = bf2_to_f2(xs.z), f3 = bf2_to_f2(xs.w);
        uint4 st;
        st.x = f2_to_bf2(dw * acc0[0] + iw * f0.x, dw * acc0[1] + iw * f0.y);
        st.y = f2_to_bf2(dw * acc0[2] + iw * f1.x, dw * acc0[3] + iw * f1.y);
        st.z = f2_to_bf2(dw * acc0[4] + iw * f2.x, dw * acc0[5] + iw * f2.y);
        st.w = f2_to_bf2(dw * acc0[6] + iw * f3.x, dw * acc0[7] + iw * f3.y);
        yr[lane] = st;
    }
    if (lane < 6) {
        uint4 xs = xr[32 + lane];
        float2 f0 = bf2_to_f2(xs.x), f1 = bf2_to_f2(xs.y);
        float2 f2 = bf2_to_f2(xs.z), f3 = bf2_to_f2(xs.w);
        uint4 st;
        st.x = f2_to_bf2(dw * acc1[0] + iw * f0.x, dw * acc1[1] + iw * f0.y);
        st.y = f2_to_bf2(dw * acc1[2] + iw * f1.x, dw * acc1[3] + iw * f1.y);
        st.z = f2_to_bf2(dw * acc1[4] + iw * f2.x, dw * acc1[5] + iw * f2.y);
        st.w = f2_to_bf2(dw * acc1[6] + iw * f3.x, dw * acc1[7] + iw * f3.y);
        yr[32 + lane] = st;
    }
}

// ---------------- phase 6: weight prep ----------------
__global__ void k_prep(const float* __restrict__ ipw, const float* __restrict__ ipb,
                       const float* __restrict__ opw, const float* __restrict__ opb,
                       const float* __restrict__ ow,  const float* __restrict__ ob) {
    __shared__ float vout[256];
    int t = threadIdx.x;
    float acc = 0.f;
    for (int j = 0; j < 256; j++) acc += opw[j * 256 + t] * ow[j];
    vout[t] = acc;
    __syncthreads();
    #pragma unroll
    for (int h = 0; h < 8; h++) {
        float a = 0.f;
        #pragma unroll 8
        for (int d = 0; d < 32; d++)
            a += ipw[(512 + h * 32 + d) * 256 + t] * vout[h * 32 + d];
        g_u[h * 256 + t] = a;
    }
    if (t < 8) {
        float c = 0.f;
        for (int d = 0; d < 32; d++) c += ipb[512 + t * 32 + d] * vout[t * 32 + d];
        g_c[t] = c;
    }
    if (t == 0) {
        float c = 0.f;
        for (int j = 0; j < 256; j++) c += opb[j] * ow[j];
        g_konst[0] = c + ob[0];
    }
}
__global__ void k_wconv(const float* __restrict__ ipw) {
    int i = blockIdx.x * 256 + threadIdx.x;
    if (i < 512 * 256 / 2) {
        float2 f = reinterpret_cast<const float2*>(ipw)[i];
        reinterpret_cast<__nv_bfloat162*>(g_wb)[i] = __float22bfloat162_rn(f);
    }
}
// block-diagonal GCN weight: [n=512][k=320], W_s at (n<256,k<100), W_f at (n>=256,100<=k<300)
__global__ void k_wgcn(const float* __restrict__ Ws, const float* __restrict__ Wf) {
    int i = blockIdx.x * 256 + threadIdx.x;
    if (i >= 512 * 320) return;
    int nn = i / 320, k = i % 320;
    float v = 0.f;
    if (nn < 256) { if (k < 100) v = Ws[k * 256 + nn]; }
    else          { if (k >= 100 && k < 300) v = Wf[(k - 100) * 256 + (nn - 256)]; }
    g_wg[i] = __float2bfloat16(v);
}

// ---------------- phase 7: GCN GEMM via HMMA -> bf16 comb ----------------
// 64 nodes/block; A [64][328] bf16 (K=320 padded), B chunks [512][72], 5 chunks of 64k.
#define GA_PAD 328
#define GB_PAD 72
#define GSM_A    0
#define GSM_B    41984
#define GSM_BIAS (GSM_B + 73728)
#define GSM_TOTAL (GSM_BIAS + 2048)

__global__ __launch_bounds__(256, 1) void k_gcn(
        const float* __restrict__ bsg, const float* __restrict__ bfg, int n) {
    extern __shared__ __align__(1024) unsigned char smraw[];
    __nv_bfloat16* A = reinterpret_cast<__nv_bfloat16*>(smraw + GSM_A);
    __nv_bfloat16* B = reinterpret_cast<__nv_bfloat16*>(smraw + GSM_B);
    float* sbias     = reinterpret_cast<float*>(smraw + GSM_BIAS);

    int tid = threadIdx.x, wid = tid >> 5, lane = tid & 31;
    int n0 = blockIdx.x * 64;

    sbias[tid]       = bsg[tid];
    sbias[256 + tid] = bfg[tid];

    // load A: 64 rows x 40 uint4 (320 bf16); source rows have 38 uint4
    for (int i = tid; i < 64 * 40; i += 256) {
        int tok = i / 40, k4 = i % 40;
        int node = n0 + tok;
        uint4 v = make_uint4(0u, 0u, 0u, 0u);
        if (node < n && k4 < 38)
            v = *reinterpret_cast<const uint4*>(&g_yb[(size_t)node * XB_PAD + k4 * 8]);
        *reinterpret_cast<uint4*>(&A[tok * GA_PAD + k4 * 8]) = v;
    }

    uint32_t a_base = smem_u32(A);
    uint32_t b_base = smem_u32(B);

    int mt = wid & 3;
    int nh = wid >> 2;

    float acc[32][4];
    #pragma unroll
    for (int j = 0; j < 32; j++)
        #pragma unroll
        for (int r = 0; r < 4; r++) acc[j][r] = 0.f;

    int a_row  = mt * 16 + (lane & 15);
    int a_col8 = (lane >> 4) * 8;
    int b_rofs = (lane & 7) + (lane >> 4) * 8;
    int b_col8 = ((lane >> 3) & 1) * 8;

    for (int c = 0; c < 5; c++) {
        __syncthreads();
        #pragma unroll
        for (int it = 0; it < 32; it++) {
            int i = it * 256 + tid;
            int rr = i >> 4, k4 = i & 15;
            unsigned long long v = *reinterpret_cast<const unsigned long long*>(
                &g_wg[rr * 320 + c * 64 + k4 * 4]);
            *reinterpret_cast<unsigned long long*>(&B[rr * GB_PAD + k4 * 4]) = v;
        }
        __syncthreads();

        #pragma unroll
        for (int ks = 0; ks < 4; ks++) {
            uint32_t af[4];
            uint32_t aaddr = a_base +
                (uint32_t)(a_row * GA_PAD + c * 64 + ks * 16 + a_col8) * 2;
            ldsm4(af[0], af[1], af[2], af[3], aaddr);
            #pragma unroll
            for (int j = 0; j < 16; j++) {
                int nrow = nh * 256 + j * 16 + b_rofs;
                uint32_t baddr = b_base +
                    (uint32_t)(nrow * GB_PAD + ks * 16 + b_col8) * 2;
                uint32_t b0, b1, b2, b3;
                ldsm4(b0, b1, b2, b3, baddr);
                mma16816(acc[2 * j],     af, b0, b1);
                mma16816(acc[2 * j + 1], af, b2, b3);
            }
        }
    }

    // epilogue: bias + relu + bf16 -> g_sfb[node*512 + col]
    int r0 = mt * 16 + (lane >> 2);
    int node0 = n0 + r0, node1 = node0 + 8;
    int cofs = (lane & 3) * 2;
    #pragma unroll
    for (int j = 0; j < 32; j++) {
        int col = nh * 256 + j * 8 + cofs;
        float b0 = sbias[col], b1 = sbias[col + 1];
        if (node0 < n) {
            uint32_t p = f2_to_bf2(fmaxf(acc[j][0] + b0, 0.f),
                                   fmaxf(acc[j][1] + b1, 0.f));
            *reinterpret_cast<uint32_t*>(&g_sfb[(size_t)node0 * 512 + col]) = p;
        }
        if (node1 < n) {
            uint32_t p = f2_to_bf2(fmaxf(acc[j][2] + b0, 0.f),
                                   fmaxf(acc[j][3] + b1, 0.f));
            *reinterpret_cast<uint32_t*>(&g_sfb[(size_t)node1 * 512 + col]) = p;
        }
    }
}

// ---------------- phase 8: HMMA QK projection + attention (unchanged) --------
#define AT_PAD 264
#define BT_PAD 72
#define SM_A    0
#define SM_BO   33792
#define SM_US   (SM_BO + 133120)
#define SM_DV   (SM_US + 8192)
#define SM_BIAS (SM_DV + 2048)
#define SM_RED  (SM_BIAS + 2048)
#define SM_TOTAL (SM_RED + 32)

__global__ __launch_bounds__(256, 1) void k_attn(
        const float* __restrict__ ipb, int n) {
    extern __shared__ __align__(1024) unsigned char smraw[];
    __nv_bfloat16* A  = reinterpret_cast<__nv_bfloat16*>(smraw + SM_A);
    __nv_bfloat16* B  = reinterpret_cast<__nv_bfloat16*>(smraw + SM_BO);
    float* Out   = reinterpret_cast<float*>(smraw + SM_BO);
    float* us    = reinterpret_cast<float*>(smraw + SM_US);
    float* dvS   = reinterpret_cast<float*>(smraw + SM_DV);
    float* sbias = reinterpret_cast<float*>(smraw + SM_BIAS);
    float* red   = reinterpret_cast<float*>(smraw + SM_RED);

    int tid = threadIdx.x, wid = tid >> 5, lane = tid & 31;
    int n0 = blockIdx.x * 32;

    for (int i = tid; i < 2048; i += 256) {
        int h = i >> 8, k = i & 255;
        us[k * 8 + h] = g_u[i];
    }
    for (int i = tid; i < 512; i += 256) sbias[i] = ipb[i];

    #pragma unroll
    for (int it = 0; it < 16; it++) {
        int i = it * 256 + tid;
        int tok = i >> 6, k4 = i & 63;
        int node = n0 + (tok >> 1);
        unsigned long long v = 0ull;
        if (node < n)
            v = *reinterpret_cast<const unsigned long long*>(
                    &g_sfb[(size_t)node * 512 + (tok & 1) * 256 + k4 * 4]);
        *reinterpret_cast<unsigned long long*>(&A[tok * AT_PAD + k4 * 4]) = v;
    }

    uint32_t a_base = smem_u32(A);
    uint32_t b_base = smem_u32(B);

    int mt = wid & 3;
    int nh = wid >> 2;

    float acc[32][4];
    #pragma unroll
    for (int j = 0; j < 32; j++)
        #pragma unroll
        for (int r = 0; r < 4; r++) acc[j][r] = 0.f;

    int a_row = mt * 16 + (lane & 15);
    int a_col8 = (lane >> 4) * 8;
    int b_rofs = (lane & 7) + (lane >> 4) * 8;
    int b_col8 = ((lane >> 3) & 1) * 8;

    for (int c = 0; c < 4; c++) {
        __syncthreads();
        #pragma unroll
        for (int it = 0; it < 32; it++) {
            int i = it * 256 + tid;
            int rr = i >> 4, k4 = i & 15;
            unsigned long long v = *reinterpret_cast<const unsigned long long*>(
                &g_wb[rr * 256 + c * 64 + k4 * 4]);
            *reinterpret_cast<unsigned long long*>(&B[rr * BT_PAD + k4 * 4]) = v;
        }
        __syncthreads();

        #pragma unroll
        for (int ks = 0; ks < 4; ks++) {
            uint32_t af[4];
            uint32_t aaddr = a_base +
                (uint32_t)(a_row * AT_PAD + c * 64 + ks * 16 + a_col8) * 2;
            ldsm4(af[0], af[1], af[2], af[3], aaddr);
            #pragma unroll
            for (int j = 0; j < 16; j++) {
                int nrow = nh * 256 + j * 16 + b_rofs;
                uint32_t baddr = b_base +
                    (uint32_t)(nrow * BT_PAD + ks * 16 + b_col8) * 2;
                uint32_t b0, b1, b2, b3;
                ldsm4(b0, b1, b2, b3, baddr);
                mma16816(acc[2 * j],     af, b0, b1);
                mma16816(acc[2 * j + 1], af, b2, b3);
            }
        }
    }
    __syncthreads();

    {
        int row0 = mt * 16 + (lane >> 2);
        int cofs = (lane & 3) * 2;
        #pragma unroll
        for (int j = 0; j < 32; j++) {
            int col = nh * 256 + j * 8 + cofs;
            float bb0 = sbias[col], bb1 = sbias[col + 1];
            Out[row0 * 520 + col]           = acc[j][0] + bb0;
            Out[row0 * 520 + col + 1]       = acc[j][1] + bb1;
            Out[(row0 + 8) * 520 + col]     = acc[j][2] + bb0;
            Out[(row0 + 8) * 520 + col + 1] = acc[j][3] + bb1;
        }
    }

    #pragma unroll
    for (int rep = 0; rep < 2; rep++) {
        int di = rep * 256 + tid;
        int tok = di >> 3, h = di & 7;
        const __nv_bfloat16* ar = &A[tok * AT_PAD];
        float a = 0.f;
        #pragma unroll 4
        for (int k = 0; k < 256; k += 2) {
            float2 f = __bfloat1622float2(
                *reinterpret_cast<const __nv_bfloat162*>(&ar[k]));
            a += f.x * us[k * 8 + h] + f.y * us[(k + 1) * 8 + h];
        }
        dvS[tok * 8 + h] = a + g_c[h];
    }
    __syncthreads();

    int node = tid >> 3, h = tid & 7;
    const float* q0 = &Out[(node * 2 + 0) * 520 + h * 32];
    const float* q1 = &Out[(node * 2 + 1) * 520 + h * 32];
    const float* k0 = &Out[(node * 2 + 0) * 520 + 256 + h * 32];
    const float* k1 = &Out[(node * 2 + 1) * 520 + 256 + h * 32];
    float s00 = 0.f, s01 = 0.f, s10 = 0.f, s11 = 0.f;
    #pragma unroll
    for (int d = 0; d < 32; d++) {
        float a0 = q0[d], a1 = q1[d], b0 = k0[d], b1 = k1[d];
        s00 += a0 * b0; s01 += a0 * b1; s10 += a1 * b0; s11 += a1 * b1;
    }
    const float scale = 0.17677669529663687f;
    s00 *= scale; s01 *= scale; s10 *= scale; s11 *= scale;
    float m0 = fmaxf(s00, s01), m1 = fmaxf(s10, s11);
    float e00 = expf(s00 - m0), e01 = expf(s01 - m0);
    float e10 = expf(s10 - m1), e11 = expf(s11 - m1);
    float d0 = e00 + e01, d1 = e10 + e11;
    float a00 = e00 / d0, a01 = e01 / d0;
    float a10 = e10 / d1, a11 = e11 / d1;
    float dv0 = dvS[(node * 2) * 8 + h];
    float dv1 = dvS[(node * 2 + 1) * 8 + h];
    float contrib = 0.5f * ((a00 + a10) * dv0 + (a01 + a11) * dv1);
    if (n0 + node >= n) contrib = 0.f;

    #pragma unroll
    for (int off = 16; off; off >>= 1)
        contrib += __shfl_xor_sync(0xffffffffu, contrib, off);
    if (lane == 0) red[wid] = contrib;
    __syncthreads();
    if (tid == 0) {
        float s = 0.f;
        #pragma unroll
        for (int w = 0; w < 8; w++) s += red[w];
        atomicAdd(&g_acc[0], s);
    }
}

// ---------------- phase 9: final scalar ----------------
__global__ void k_final(float* __restrict__ out, int n) {
    out[0] = g_acc[0] / (float)n + g_konst[0];
}

// ---------------- launch ----------------
extern "C" void kernel_launch(void* const* d_in, const int* in_sizes, int n_in,
                              void* d_out, int out_size) {
    const float* x   = (const float*)d_in[0];
    const int*   ei  = (const int*)d_in[1];
    const float* W_s = (const float*)d_in[2];
    const float* b_s = (const float*)d_in[3];
    const float* W_f = (const float*)d_in[4];
    const float* b_f = (const float*)d_in[5];
    const float* ipw = (const float*)d_in[6];
    const float* ipb = (const float*)d_in[7];
    const float* opw = (const float*)d_in[8];
    const float* opb = (const float*)d_in[9];
    const float* ow  = (const float*)d_in[10];
    const float* ob  = (const float*)d_in[11];

    int n = in_sizes[0] / FEAT;
    int E = in_sizes[1] / 2;
    int nb = (n + 255) / 256;

    k_zero<<<(n + 255) / 256, 256>>>(n);
    k_deg<<<(E + 255) / 256, 256>>>(ei, E);
    k_dis<<<(n + 255) / 256, 256>>>(n);
    k_scanA<<<nb, 256>>>(n);
    k_scanB<<<1, 256>>>(nb, n);
    k_scanC<<<nb, 256>>>(n);
    k_scatter<<<(E + 255) / 256, 256>>>(ei, E);
    k_xconv<<<(n * 152 + 255) / 256, 256>>>(x, n);
    k_gather<<<(n + 7) / 8, 256>>>(n);
    k_prep<<<1, 256>>>(ipw, ipb, opw, opb, ow, ob);
    k_wconv<<<256, 256>>>(ipw);
    k_wgcn<<<(512 * 320 + 255) / 256, 256>>>(W_s, W_f);

    cudaFuncSetAttribute(k_gcn, cudaFuncAttributeMaxDynamicSharedMemorySize, GSM_TOTAL);
    k_gcn<<<(n + 63) / 64, 256, GSM_TOTAL>>>(b_s, b_f, n);

    cudaFuncSetAttribute(k_attn, cudaFuncAttributeMaxDynamicSharedMemorySize, SM_TOTAL);
    k_attn<<<(n + 31) / 32, 256, SM_TOTAL>>>(ipb, n);

    k_final<<<1, 1>>>((float*)d_out, n);
}

// round 9
// speedup vs baseline: 3.3962x; 1.0870x over previous
#include <cuda_runtime.h>
#include <cuda_bf16.h>
#include <cstdint>

#define N_NODES_MAX 50000
#define E_MAX 1600000
#define FEAT 300
#define XB_PAD 304              // padded bf16 row (38 uint4)
#define HID 256

// ---------------- device scratch ----------------
__device__ int   g_degi[N_NODES_MAX];
__device__ int   g_off [N_NODES_MAX + 1];
__device__ int   g_cur [N_NODES_MAX];
__device__ int   g_srcs[E_MAX];
__device__ int   g_bsum[256];
__device__ int   g_bpre[256];
__device__ __align__(16) float g_dis [N_NODES_MAX];
__device__ __align__(16) float g_dinv[N_NODES_MAX];
__device__ __align__(16) __nv_bfloat16 g_xb [N_NODES_MAX * XB_PAD];  // x bf16 padded
__device__ __align__(16) __nv_bfloat16 g_yb [N_NODES_MAX * XB_PAD];  // y = dis*agg+dinv*x
__device__ __align__(16) __nv_bfloat16 g_sfb[N_NODES_MAX * 2 * HID]; // comb bf16
__device__ __align__(16) __nv_bfloat16 g_wb2[544 * 256];             // QK weights + u_hi + u_lo
__device__ __align__(16) __nv_bfloat16 g_wg [512 * 320];             // block-diag GCN W bf16
__device__ __align__(16) float g_u   [8 * 256];
__device__ __align__(16) float g_c   [8];
__device__ float g_konst[1];
__device__ float g_acc [1];

// ---------------- helpers ----------------
__device__ __forceinline__ float2 bf2_to_f2(uint32_t u) {
    float2 r;
    r.x = __uint_as_float(u << 16);
    r.y = __uint_as_float(u & 0xffff0000u);
    return r;
}
__device__ __forceinline__ uint32_t f2_to_bf2(float a, float b) {
    __nv_bfloat162 p = __float22bfloat162_rn(make_float2(a, b));
    return *reinterpret_cast<uint32_t*>(&p);
}
__device__ __forceinline__ uint32_t smem_u32(const void* p) {
    uint32_t a;
    asm("{ .reg .u64 t; cvta.to.shared.u64 t, %1; cvt.u32.u64 %0, t; }"
        : "=r"(a) : "l"(p));
    return a;
}
__device__ __forceinline__ void ldsm4(uint32_t& r0, uint32_t& r1,
                                      uint32_t& r2, uint32_t& r3, uint32_t addr) {
    asm volatile("ldmatrix.sync.aligned.m8n8.x4.shared.b16 {%0,%1,%2,%3}, [%4];"
                 : "=r"(r0), "=r"(r1), "=r"(r2), "=r"(r3) : "r"(addr));
}
__device__ __forceinline__ void mma16816(float* d, const uint32_t* a,
                                         uint32_t b0, uint32_t b1) {
    asm volatile(
        "mma.sync.aligned.m16n8k16.row.col.f32.bf16.bf16.f32 "
        "{%0,%1,%2,%3}, {%4,%5,%6,%7}, {%8,%9}, {%0,%1,%2,%3};"
        : "+f"(d[0]), "+f"(d[1]), "+f"(d[2]), "+f"(d[3])
        : "r"(a[0]), "r"(a[1]), "r"(a[2]), "r"(a[3]), "r"(b0), "r"(b1));
}
__device__ __forceinline__ void cp16(uint32_t smem_dst, const void* gsrc) {
    asm volatile("cp.async.cg.shared.global [%0], [%1], 16;"
                 :: "r"(smem_dst), "l"(gsrc) : "memory");
}
#define CP_COMMIT() asm volatile("cp.async.commit_group;" ::: "memory")
#define CP_WAIT(N)  asm volatile("cp.async.wait_group %0;" :: "n"(N) : "memory")

// ---------------- phases 0-4: degree, CSR ----------------
__global__ void k_zero(int n) {
    int i = blockIdx.x * blockDim.x + threadIdx.x;
    if (i < n) g_degi[i] = 0;
    if (i == 0) g_acc[0] = 0.f;
}
__global__ void k_deg(const int* __restrict__ ei, int E) {
    int i = blockIdx.x * blockDim.x + threadIdx.x;
    if (i < E) atomicAdd(&g_degi[ei[E + i]], 1);
}
__global__ void k_dis(int n) {
    int i = blockIdx.x * blockDim.x + threadIdx.x;
    if (i < n) {
        float d = 1.0f + (float)g_degi[i];
        g_dis[i]  = rsqrtf(d);
        g_dinv[i] = 1.0f / d;
    }
}
__global__ void k_scanA(int n) {
    __shared__ int sh[8];
    int i = blockIdx.x * 256 + threadIdx.x;
    int v = (i < n) ? g_degi[i] : 0;
    #pragma unroll
    for (int off = 16; off; off >>= 1) v += __shfl_xor_sync(0xffffffffu, v, off);
    if ((threadIdx.x & 31) == 0) sh[threadIdx.x >> 5] = v;
    __syncthreads();
    if (threadIdx.x == 0) {
        int s = 0;
        #pragma unroll
        for (int w = 0; w < 8; w++) s += sh[w];
        g_bsum[blockIdx.x] = s;
    }
}
__global__ void k_scanB(int nb, int n) {
    __shared__ int sh[256];
    int t = threadIdx.x;
    int v = (t < nb) ? g_bsum[t] : 0;
    sh[t] = v;
    __syncthreads();
    #pragma unroll
    for (int off = 1; off < 256; off <<= 1) {
        int u = (t >= off) ? sh[t - off] : 0;
        __syncthreads();
        sh[t] += u;
        __syncthreads();
    }
    if (t < nb) g_bpre[t] = sh[t] - v;
    if (t == nb - 1) g_off[n] = sh[t];
}
__global__ void k_scanC(int n) {
    __shared__ int sh[256];
    int t = threadIdx.x;
    int i = blockIdx.x * 256 + t;
    int v = (i < n) ? g_degi[i] : 0;
    sh[t] = v;
    __syncthreads();
    #pragma unroll
    for (int off = 1; off < 256; off <<= 1) {
        int u = (t >= off) ? sh[t - off] : 0;
        __syncthreads();
        sh[t] += u;
        __syncthreads();
    }
    if (i < n) {
        int off = g_bpre[blockIdx.x] + sh[t] - v;
        g_off[i] = off;
        g_cur[i] = off;
    }
}
__global__ void k_scatter(const int* __restrict__ ei, int E) {
    int i = blockIdx.x * blockDim.x + threadIdx.x;
    if (i >= E) return;
    int s = ei[i];
    int d = ei[E + i];
    int pos = atomicAdd(&g_cur[d], 1);
    g_srcs[pos] = s;
}

// ---------------- phase 5a: x -> bf16 padded ----------------
__global__ void k_xconv(const float* __restrict__ x, int n) {
    int i = blockIdx.x * 256 + threadIdx.x;
    if (i >= n * 152) return;
    int row = i / 152, p = i % 152;
    uint32_t v = 0;
    if (p < 150) {
        float2 f = *reinterpret_cast<const float2*>(&x[row * FEAT + 2 * p]);
        v = f2_to_bf2(f.x, f.y);
    }
    *reinterpret_cast<uint32_t*>(&g_xb[row * XB_PAD + 2 * p]) = v;
}

// ---------------- phase 5b: gather-aggregate + y epilogue ----------------
__global__ __launch_bounds__(256) void k_gather(int n) {
    int w    = (blockIdx.x * blockDim.x + threadIdx.x) >> 5;
    int lane = threadIdx.x & 31;
    if (w >= n) return;
    int beg = g_off[w], end = g_off[w + 1];

    float acc0[8], acc1[8];
    #pragma unroll
    for (int j = 0; j < 8; j++) { acc0[j] = 0.f; acc1[j] = 0.f; }

    for (int base = beg; base < end; base += 32) {
        int cnt = min(32, end - base);
        int   s_l = 0;
        float w_l = 0.f;
        if (lane < cnt) {
            s_l = g_srcs[base + lane];
            w_l = g_dis[s_l];
        }
        for (int k = 0; k < cnt; k++) {
            int   s  = __shfl_sync(0xffffffffu, s_l, k);
            float wt = __shfl_sync(0xffffffffu, w_l, k);
            const uint4* xr = reinterpret_cast<const uint4*>(g_xb + (size_t)s * XB_PAD);
            uint4 v = __ldg(&xr[lane]);
            float2 f;
            f = bf2_to_f2(v.x); acc0[0] += wt * f.x; acc0[1] += wt * f.y;
            f = bf2_to_f2(v.y); acc0[2] += wt * f.x; acc0[3] += wt * f.y;
            f = bf2_to_f2(v.z); acc0[4] += wt * f.x; acc0[5] += wt * f.y;
            f = bf2_to_f2(v.w); acc0[6] += wt * f.x; acc0[7] += wt * f.y;
            if (lane < 6) {
                uint4 v2 = __ldg(&xr[32 + lane]);
                f = bf2_to_f2(v2.x); acc1[0] += wt * f.x; acc1[1] += wt * f.y;
                f = bf2_to_f2(v2.y); acc1[2] += wt * f.x; acc1[3] += wt * f.y;
                f = bf2_to_f2(v2.z); acc1[4] += wt * f.x; acc1[5] += wt * f.y;
                f = bf2_to_f2(v2.w); acc1[6] += wt * f.x; acc1[7] += wt * f.y;
            }
        }
    }

    float dw = g_dis[w], iw = g_dinv[w];
    const uint4* xr = reinterpret_cast<const uint4*>(g_xb + (size_t)w * XB_PAD);
    uint4* yr = reinterpret_cast<uint4*>(g_yb + (size_t)w * XB_PAD);
    {
        uint4 xs = xr[lane];
        float2 f0 = bf2_to_f2(xs.x), f1 = bf2_to_f2(xs.y);
        float2 f2 = bf2_to_f2(xs.z), f3 = bf2_to_f2(xs.w);
        uint4 st;
        st.x = f2_to_bf2(dw * acc0[0] + iw * f0.x, dw * acc0[1] + iw * f0.y);
        st.y = f2_to_bf2(dw * acc0[2] + iw * f1.x, dw * acc0[3] + iw * f1.y);
        st.z = f2_to_bf2(dw * acc0[4] + iw * f2.x, dw * acc0[5] + iw * f2.y);
        st.w = f2_to_bf2(dw * acc0[6] + iw * f3.x, dw * acc0[7] + iw * f3.y);
        yr[lane] = st;
    }
    if (lane < 6) {
        uint4 xs = xr[32 + lane];
        float2 f0 = bf2_to_f2(xs.x), f1 = bf2_to_f2(xs.y);
        float2 f2 = bf2_to_f2(xs.z), f3 = bf2_to_f2(xs.w);
        uint4 st;
        st.x = f2_to_bf2(dw * acc1[0] + iw * f0.x, dw * acc1[1] + iw * f0.y);
        st.y = f2_to_bf2(dw * acc1[2] + iw * f1.x, dw * acc1[3] + iw * f1.y);
        st.z = f2_to_bf2(dw * acc1[4] + iw * f2.x, dw * acc1[5] + iw * f2.y);
        st.w = f2_to_bf2(dw * acc1[6] + iw * f3.x, dw * acc1[7] + iw * f3.y);
        yr[32 + lane] = st;
    }
}

// ---------------- phase 6: weight prep ----------------
__global__ void k_prep(const float* __restrict__ ipw, const float* __restrict__ ipb,
                       const float* __restrict__ opw, const float* __restrict__ opb,
                       const float* __restrict__ ow,  const float* __restrict__ ob) {
    __shared__ float vout[256];
    int t = threadIdx.x;
    float acc = 0.f;
    for (int j = 0; j < 256; j++) acc += opw[j * 256 + t] * ow[j];
    vout[t] = acc;
    __syncthreads();
    #pragma unroll
    for (int h = 0; h < 8; h++) {
        float a = 0.f;
        #pragma unroll 8
        for (int d = 0; d < 32; d++)
            a += ipw[(512 + h * 32 + d) * 256 + t] * vout[h * 32 + d];
        g_u[h * 256 + t] = a;
    }
    if (t < 8) {
        float c = 0.f;
        for (int d = 0; d < 32; d++) c += ipb[512 + t * 32 + d] * vout[t * 32 + d];
        g_c[t] = c;
    }
    if (t == 0) {
        float c = 0.f;
        for (int j = 0; j < 256; j++) c += opb[j] * ow[j];
        g_konst[0] = c + ob[0];
    }
}
// wb2 rows: 0:512 = ipw (Q,K); 512:520 = u_hi = bf16(u); 520:528 = u_lo =
// bf16(u - u_hi)  (two-term split: u is SHARED by all nodes, its quantization
// error is a fixed bias that does NOT average out in the pool); 528:544 = 0.
__global__ void k_wconv2(const float* __restrict__ ipw) {
    int i = blockIdx.x * 256 + threadIdx.x;   // over 544*128 bf16-pairs
    if (i >= 544 * 128) return;
    int r = i / 128, p = i % 128;
    float a = 0.f, b = 0.f;
    if (r < 512) {
        a = ipw[r * 256 + 2 * p];
        b = ipw[r * 256 + 2 * p + 1];
    } else if (r < 520) {
        a = g_u[(r - 512) * 256 + 2 * p];
        b = g_u[(r - 512) * 256 + 2 * p + 1];
    } else if (r < 528) {
        float ua = g_u[(r - 520) * 256 + 2 * p];
        float ub = g_u[(r - 520) * 256 + 2 * p + 1];
        a = ua - __bfloat162float(__float2bfloat16(ua));
        b = ub - __bfloat162float(__float2bfloat16(ub));
    }
    *reinterpret_cast<uint32_t*>(&g_wb2[r * 256 + 2 * p]) = f2_to_bf2(a, b);
}
__global__ void k_wgcn(const float* __restrict__ Ws, const float* __restrict__ Wf) {
    int i = blockIdx.x * 256 + threadIdx.x;
    if (i >= 512 * 320) return;
    int nn = i / 320, k = i % 320;
    float v = 0.f;
    if (nn < 256) { if (k < 100) v = Ws[k * 256 + nn]; }
    else          { if (k >= 100 && k < 300) v = Wf[(k - 100) * 256 + (nn - 256)]; }
    g_wg[i] = __float2bfloat16(v);
}

// ---------------- phase 7: GCN GEMM via HMMA (cp.async double-buffered) ------
#define GA_PAD 328
#define GB_ROWB 144                          // 72 bf16 per row
#define G_SM_A   0                           // 64 x 328 x 2 = 41984
#define G_SM_B0  41984
#define G_B_BYTES 73728                      // 512 x 144
#define G_SM_B1  (G_SM_B0 + G_B_BYTES)
#define G_SM_BIAS (G_SM_B1 + G_B_BYTES)      // 189440
#define G_SM_TOTAL (G_SM_BIAS + 2048)

__global__ __launch_bounds__(256, 1) void k_gcn(
        const float* __restrict__ bsg, const float* __restrict__ bfg, int n) {
    extern __shared__ __align__(1024) unsigned char smraw[];
    __nv_bfloat16* A = reinterpret_cast<__nv_bfloat16*>(smraw + G_SM_A);
    float* sbias     = reinterpret_cast<float*>(smraw + G_SM_BIAS);

    int tid = threadIdx.x, wid = tid >> 5, lane = tid & 31;
    int n0 = blockIdx.x * 64;

    uint32_t b0_base = smem_u32(smraw + G_SM_B0);
    uint32_t b1_base = smem_u32(smraw + G_SM_B1);

    #pragma unroll
    for (int it = 0; it < 16; it++) {
        int i = it * 256 + tid;
        int rr = i >> 3, k4 = i & 7;
        cp16(b0_base + rr * GB_ROWB + k4 * 16, &g_wg[rr * 320 + 0 * 64 + k4 * 8]);
    }
    CP_COMMIT();
    #pragma unroll
    for (int it = 0; it < 16; it++) {
        int i = it * 256 + tid;
        int rr = i >> 3, k4 = i & 7;
        cp16(b1_base + rr * GB_ROWB + k4 * 16, &g_wg[rr * 320 + 1 * 64 + k4 * 8]);
    }
    CP_COMMIT();

    sbias[tid]       = bsg[tid];
    sbias[256 + tid] = bfg[tid];

    for (int i = tid; i < 64 * 40; i += 256) {
        int tok = i / 40, k4 = i % 40;
        int node = n0 + tok;
        uint4 v = make_uint4(0u, 0u, 0u, 0u);
        if (node < n && k4 < 38)
            v = *reinterpret_cast<const uint4*>(&g_yb[(size_t)node * XB_PAD + k4 * 8]);
        *reinterpret_cast<uint4*>(&A[tok * GA_PAD + k4 * 8]) = v;
    }

    uint32_t a_base = smem_u32(A);
    int mt = wid & 3;
    int nh = wid >> 2;

    float acc[32][4];
    #pragma unroll
    for (int j = 0; j < 32; j++)
        #pragma unroll
        for (int r = 0; r < 4; r++) acc[j][r] = 0.f;

    int a_row  = mt * 16 + (lane & 15);
    int a_col8 = (lane >> 4) * 8;
    int b_rofs = (lane & 7) + (lane >> 4) * 8;
    int b_col8 = ((lane >> 3) & 1) * 8;

    for (int c = 0; c < 5; c++) {
        if (c < 4) CP_WAIT(1); else CP_WAIT(0);
        __syncthreads();
        uint32_t b_base = (c & 1) ? b1_base : b0_base;

        #pragma unroll
        for (int ks = 0; ks < 4; ks++) {
            uint32_t af[4];
            uint32_t aaddr = a_base +
                (uint32_t)(a_row * GA_PAD + c * 64 + ks * 16 + a_col8) * 2;
            ldsm4(af[0], af[1], af[2], af[3], aaddr);
            #pragma unroll
            for (int j = 0; j < 16; j++) {
                int nrow = nh * 256 + j * 16 + b_rofs;
                uint32_t baddr = b_base + nrow * GB_ROWB + ks * 32 + b_col8 * 2;
                uint32_t b0, b1, b2, b3;
                ldsm4(b0, b1, b2, b3, baddr);
                mma16816(acc[2 * j],     af, b0, b1);
                mma16816(acc[2 * j + 1], af, b2, b3);
            }
        }
        if (c + 2 < 5) {
            __syncthreads();
            uint32_t dstb = (c & 1) ? b1_base : b0_base;
            #pragma unroll
            for (int it = 0; it < 16; it++) {
                int i = it * 256 + tid;
                int rr = i >> 3, k4 = i & 7;
                cp16(dstb + rr * GB_ROWB + k4 * 16,
                     &g_wg[rr * 320 + (c + 2) * 64 + k4 * 8]);
            }
            CP_COMMIT();
        }
    }

    int r0 = mt * 16 + (lane >> 2);
    int node0 = n0 + r0, node1 = node0 + 8;
    int cofs = (lane & 3) * 2;
    #pragma unroll
    for (int j = 0; j < 32; j++) {
        int col = nh * 256 + j * 8 + cofs;
        float b0 = sbias[col], b1 = sbias[col + 1];
        if (node0 < n) {
            uint32_t p = f2_to_bf2(fmaxf(acc[j][0] + b0, 0.f),
                                   fmaxf(acc[j][1] + b1, 0.f));
            *reinterpret_cast<uint32_t*>(&g_sfb[(size_t)node0 * 512 + col]) = p;
        }
        if (node1 < n) {
            uint32_t p = f2_to_bf2(fmaxf(acc[j][2] + b0, 0.f),
                                   fmaxf(acc[j][3] + b1, 0.f));
            *reinterpret_cast<uint32_t*>(&g_sfb[(size_t)node1 * 512 + col]) = p;
        }
    }
}

// ---------------- phase 8: HMMA QK+dv projection + attention -----------------
// 32 nodes = 64 tok/block. B = 544 rows (Q 0:256, K 256:512, u_hi 512:520,
// u_lo 520:528, pad). Out fp32 [64][552] unioned over B double-buffers.
#define AT_PAD 264
#define AB_ROWB 144
#define OUT_PAD 552
#define A_SM_A   0                            // 64 x 264 x 2 = 33792
#define A_SM_B0  33792
#define A_B_BYTES 78336                       // 544 x 144
#define A_SM_B1  (A_SM_B0 + A_B_BYTES)        // 112128
#define A_SM_BIAS 190464                      // 544 x 4 = 2176
#define A_SM_RED  (A_SM_BIAS + 2176)
#define A_SM_TOTAL (A_SM_RED + 64)

__global__ __launch_bounds__(256, 1) void k_attn(
        const float* __restrict__ ipb, int n) {
    extern __shared__ __align__(1024) unsigned char smraw[];
    __nv_bfloat16* A = reinterpret_cast<__nv_bfloat16*>(smraw + A_SM_A);
    float* Out   = reinterpret_cast<float*>(smraw + A_SM_B0);
    float* sbias = reinterpret_cast<float*>(smraw + A_SM_BIAS);
    float* red   = reinterpret_cast<float*>(smraw + A_SM_RED);

    int tid = threadIdx.x, wid = tid >> 5, lane = tid & 31;
    int n0 = blockIdx.x * 32;

    uint32_t b0_base = smem_u32(smraw + A_SM_B0);
    uint32_t b1_base = smem_u32(smraw + A_SM_B1);

    #pragma unroll
    for (int it = 0; it < 17; it++) {
        int i = it * 256 + tid;
        int rr = i >> 3, k4 = i & 7;
        cp16(b0_base + rr * AB_ROWB + k4 * 16, &g_wb2[rr * 256 + 0 * 64 + k4 * 8]);
    }
    CP_COMMIT();
    #pragma unroll
    for (int it = 0; it < 17; it++) {
        int i = it * 256 + tid;
        int rr = i >> 3, k4 = i & 7;
        cp16(b1_base + rr * AB_ROWB + k4 * 16, &g_wb2[rr * 256 + 1 * 64 + k4 * 8]);
    }
    CP_COMMIT();

    // bias: 0:512 = ipb, 512:520 = g_c, rest 0 (u_lo rows get no bias)
    for (int i = tid; i < 544; i += 256) {
        float v = 0.f;
        if (i < 512) v = ipb[i];
        else if (i < 520) v = g_c[i - 512];
        sbias[i] = v;
    }

    #pragma unroll
    for (int it = 0; it < 16; it++) {
        int i = it * 256 + tid;
        int tok = i >> 6, k4 = i & 63;
        int node = n0 + (tok >> 1);
        unsigned long long v = 0ull;
        if (node < n)
            v = *reinterpret_cast<const unsigned long long*>(
                    &g_sfb[(size_t)node * 512 + (tok & 1) * 256 + k4 * 4]);
        *reinterpret_cast<unsigned long long*>(&A[tok * AT_PAD + k4 * 4]) = v;
    }

    uint32_t a_base = smem_u32(A);
    int mt = wid & 3;
    int nh = wid >> 2;

    float acc[34][4];
    #pragma unroll
    for (int j = 0; j < 34; j++)
        #pragma unroll
        for (int r = 0; r < 4; r++) acc[j][r] = 0.f;

    int a_row = mt * 16 + (lane & 15);
    int a_col8 = (lane >> 4) * 8;
    int b_rofs = (lane & 7) + (lane >> 4) * 8;
    int b_col8 = ((lane >> 3) & 1) * 8;

    for (int c = 0; c < 4; c++) {
        if (c < 3) CP_WAIT(1); else CP_WAIT(0);
        __syncthreads();
        uint32_t b_base = (c & 1) ? b1_base : b0_base;

        #pragma unroll
        for (int ks = 0; ks < 4; ks++) {
            uint32_t af[4];
            uint32_t aaddr = a_base +
                (uint32_t)(a_row * AT_PAD + c * 64 + ks * 16 + a_col8) * 2;
            ldsm4(af[0], af[1], af[2], af[3], aaddr);
            #pragma unroll
            for (int j = 0; j < 17; j++) {
                int nrow = nh * 272 + j * 16 + b_rofs;
                uint32_t baddr = b_base + nrow * AB_ROWB + ks * 32 + b_col8 * 2;
                uint32_t b0, b1, b2, b3;
                ldsm4(b0, b1, b2, b3, baddr);
                mma16816(acc[2 * j],     af, b0, b1);
                mma16816(acc[2 * j + 1], af, b2, b3);
            }
        }
        if (c + 2 < 4) {
            __syncthreads();
            uint32_t dstb = (c & 1) ? b1_base : b0_base;
            #pragma unroll
            for (int it = 0; it < 17; it++) {
                int i = it * 256 + tid;
                int rr = i >> 3, k4 = i & 7;
                cp16(dstb + rr * AB_ROWB + k4 * 16,
                     &g_wb2[rr * 256 + (c + 2) * 64 + k4 * 8]);
            }
            CP_COMMIT();
        }
    }
    __syncthreads();   // all MMA reads done -> Out may overwrite B region

    {
        int row0 = mt * 16 + (lane >> 2);
        int cofs = (lane & 3) * 2;
        #pragma unroll
        for (int j = 0; j < 34; j++) {
            int col = nh * 272 + j * 8 + cofs;
            float bb0 = sbias[col], bb1 = sbias[col + 1];
            Out[row0 * OUT_PAD + col]           = acc[j][0] + bb0;
            Out[row0 * OUT_PAD + col + 1]       = acc[j][1] + bb1;
            Out[(row0 + 8) * OUT_PAD + col]     = acc[j][2] + bb0;
            Out[(row0 + 8) * OUT_PAD + col + 1] = acc[j][3] + bb1;
        }
    }
    __syncthreads();

    // per (node, head) 2x2 attention; dv = u_hi col + u_lo col
    int node = tid >> 3, h = tid & 7;
    const float4* q0 = reinterpret_cast<const float4*>(
        &Out[(node * 2 + 0) * OUT_PAD + h * 32]);
    const float4* q1 = reinterpret_cast<const float4*>(
        &Out[(node * 2 + 1) * OUT_PAD + h * 32]);
    const float4* k0 = reinterpret_cast<const float4*>(
        &Out[(node * 2 + 0) * OUT_PAD + 256 + h * 32]);
    const float4* k1 = reinterpret_cast<const float4*>(
        &Out[(node * 2 + 1) * OUT_PAD + 256 + h * 32]);
    float s00 = 0.f, s01 = 0.f, s10 = 0.f, s11 = 0.f;
    #pragma unroll
    for (int d = 0; d < 8; d++) {
        float4 a0 = q0[d], a1 = q1[d], b0 = k0[d], b1 = k1[d];
        s00 += a0.x * b0.x + a0.y * b0.y + a0.z * b0.z + a0.w * b0.w;
        s01 += a0.x * b1.x + a0.y * b1.y + a0.z * b1.z + a0.w * b1.w;
        s10 += a1.x * b0.x + a1.y * b0.y + a1.z * b0.z + a1.w * b0.w;
        s11 += a1.x * b1.x + a1.y * b1.y + a1.z * b1.z + a1.w * b1.w;
    }
    const float scale = 0.17677669529663687f;
    s00 *= scale; s01 *= scale; s10 *= scale; s11 *= scale;
    float m0 = fmaxf(s00, s01), m1 = fmaxf(s10, s11);
    float e00 = expf(s00 - m0), e01 = expf(s01 - m0);
    float e10 = expf(s10 - m1), e11 = expf(s11 - m1);
    float d0 = e00 + e01, d1 = e10 + e11;
    float a00 = e00 / d0, a01 = e01 / d0;
    float a10 = e10 / d1, a11 = e11 / d1;
    float dv0 = Out[(node * 2 + 0) * OUT_PAD + 512 + h]
              + Out[(node * 2 + 0) * OUT_PAD + 520 + h];
    float dv1 = Out[(node * 2 + 1) * OUT_PAD + 512 + h]
              + Out[(node * 2 + 1) * OUT_PAD + 520 + h];
    float contrib = 0.5f * ((a00 + a10) * dv0 + (a01 + a11) * dv1);
    if (n0 + node >= n) contrib = 0.f;

    #pragma unroll
    for (int off = 16; off; off >>= 1)
        contrib += __shfl_xor_sync(0xffffffffu, contrib, off);
    if (lane == 0) red[wid] = contrib;
    __syncthreads();
    if (tid == 0) {
        float s = 0.f;
        #pragma unroll
        for (int w = 0; w < 8; w++) s += red[w];
        atomicAdd(&g_acc[0], s);
    }
}

// ---------------- phase 9: final scalar ----------------
__global__ void k_final(float* __restrict__ out, int n) {
    out[0] = g_acc[0] / (float)n + g_konst[0];
}

// ---------------- launch ----------------
extern "C" void kernel_launch(void* const* d_in, const int* in_sizes, int n_in,
                              void* d_out, int out_size) {
    const float* x   = (const float*)d_in[0];
    const int*   ei  = (const int*)d_in[1];
    const float* W_s = (const float*)d_in[2];
    const float* b_s = (const float*)d_in[3];
    const float* W_f = (const float*)d_in[4];
    const float* b_f = (const float*)d_in[5];
    const float* ipw = (const float*)d_in[6];
    const float* ipb = (const float*)d_in[7];
    const float* opw = (const float*)d_in[8];
    const float* opb = (const float*)d_in[9];
    const float* ow  = (const float*)d_in[10];
    const float* ob  = (const float*)d_in[11];

    int n = in_sizes[0] / FEAT;
    int E = in_sizes[1] / 2;
    int nb = (n + 255) / 256;

    k_zero<<<(n + 255) / 256, 256>>>(n);
    k_deg<<<(E + 255) / 256, 256>>>(ei, E);
    k_dis<<<(n + 255) / 256, 256>>>(n);
    k_scanA<<<nb, 256>>>(n);
    k_scanB<<<1, 256>>>(nb, n);
    k_scanC<<<nb, 256>>>(n);
    k_scatter<<<(E + 255) / 256, 256>>>(ei, E);
    k_xconv<<<(n * 152 + 255) / 256, 256>>>(x, n);
    k_gather<<<(n + 7) / 8, 256>>>(n);
    k_prep<<<1, 256>>>(ipw, ipb, opw, opb, ow, ob);
    k_wconv2<<<(544 * 128 + 255) / 256, 256>>>(ipw);
    k_wgcn<<<(512 * 320 + 255) / 256, 256>>>(W_s, W_f);

    cudaFuncSetAttribute(k_gcn, cudaFuncAttributeMaxDynamicSharedMemorySize, G_SM_TOTAL);
    k_gcn<<<(n + 63) / 64, 256, G_SM_TOTAL>>>(b_s, b_f, n);

    cudaFuncSetAttribute(k_attn, cudaFuncAttributeMaxDynamicSharedMemorySize, A_SM_TOTAL);
    k_attn<<<(n + 31) / 32, 256, A_SM_TOTAL>>>(ipb, n);

    k_final<<<1, 1>>>((float*)d_out, n);
}

// round 10
// speedup vs baseline: 3.4660x; 1.0206x over previous
#include <cuda_runtime.h>
#include <cuda_bf16.h>
#include <cstdint>

#define N_NODES_MAX 50000
#define E_MAX 1600000
#define FEAT 300
#define XB_PAD 304              // padded bf16 row (38 uint4)
#define HID 256

// ---------------- device scratch ----------------
__device__ int   g_degi[N_NODES_MAX];
__device__ int   g_off [N_NODES_MAX + 1];
__device__ int   g_cur [N_NODES_MAX];
__device__ int   g_srcs[E_MAX];
__device__ int   g_bsum[256];
__device__ int   g_bpre[256];
__device__ __align__(16) float g_dis [N_NODES_MAX];
__device__ __align__(16) float g_dinv[N_NODES_MAX];
__device__ __align__(16) __nv_bfloat16 g_xb [N_NODES_MAX * XB_PAD];  // x bf16 padded
__device__ __align__(16) __nv_bfloat16 g_yb [N_NODES_MAX * XB_PAD];  // y = dis*agg+dinv*x
__device__ __align__(16) __nv_bfloat16 g_sfb[N_NODES_MAX * 2 * HID]; // comb bf16
__device__ __align__(16) __nv_bfloat16 g_wb2[544 * 256];             // QK weights + u_hi + u_lo
__device__ __align__(16) __nv_bfloat16 g_wg [512 * 320];             // block-diag GCN W bf16
__device__ __align__(16) float g_u   [8 * 256];
__device__ __align__(16) float g_c   [8];
__device__ float g_konst[1];
__device__ float g_acc [1];

// ---------------- helpers ----------------
__device__ __forceinline__ float2 bf2_to_f2(uint32_t u) {
    float2 r;
    r.x = __uint_as_float(u << 16);
    r.y = __uint_as_float(u & 0xffff0000u);
    return r;
}
__device__ __forceinline__ uint32_t f2_to_bf2(float a, float b) {
    __nv_bfloat162 p = __float22bfloat162_rn(make_float2(a, b));
    return *reinterpret_cast<uint32_t*>(&p);
}
__device__ __forceinline__ uint32_t smem_u32(const void* p) {
    uint32_t a;
    asm("{ .reg .u64 t; cvta.to.shared.u64 t, %1; cvt.u32.u64 %0, t; }"
        : "=r"(a) : "l"(p));
    return a;
}
__device__ __forceinline__ void ldsm4(uint32_t& r0, uint32_t& r1,
                                      uint32_t& r2, uint32_t& r3, uint32_t addr) {
    asm volatile("ldmatrix.sync.aligned.m8n8.x4.shared.b16 {%0,%1,%2,%3}, [%4];"
                 : "=r"(r0), "=r"(r1), "=r"(r2), "=r"(r3) : "r"(addr));
}
__device__ __forceinline__ void mma16816(float* d, const uint32_t* a,
                                         uint32_t b0, uint32_t b1) {
    asm volatile(
        "mma.sync.aligned.m16n8k16.row.col.f32.bf16.bf16.f32 "
        "{%0,%1,%2,%3}, {%4,%5,%6,%7}, {%8,%9}, {%0,%1,%2,%3};"
        : "+f"(d[0]), "+f"(d[1]), "+f"(d[2]), "+f"(d[3])
        : "r"(a[0]), "r"(a[1]), "r"(a[2]), "r"(a[3]), "r"(b0), "r"(b1));
}
__device__ __forceinline__ void cp16(uint32_t smem_dst, const void* gsrc) {
    asm volatile("cp.async.cg.shared.global [%0], [%1], 16;"
                 :: "r"(smem_dst), "l"(gsrc) : "memory");
}
#define CP_COMMIT() asm volatile("cp.async.commit_group;" ::: "memory")
#define CP_WAIT(N)  asm volatile("cp.async.wait_group %0;" :: "n"(N) : "memory")

// ---------------- phase 0: zero ∥ prep  (block-range fusion) ----------------
// blocks [0, nzb): zero g_degi ; block nzb: weight-fold prep (1 block)
__global__ void k_init(const float* __restrict__ ipw, const float* __restrict__ ipb,
                       const float* __restrict__ opw, const float* __restrict__ opb,
                       const float* __restrict__ ow,  const float* __restrict__ ob,
                       int n, int nzb) {
    int t = threadIdx.x;
    if ((int)blockIdx.x < nzb) {
        int i = blockIdx.x * 256 + t;
        if (i < n) g_degi[i] = 0;
        if (i == 0) g_acc[0] = 0.f;
        return;
    }
    // ---- prep (single block) ----
    __shared__ float vout[256];
    float acc = 0.f;
    for (int j = 0; j < 256; j++) acc += opw[j * 256 + t] * ow[j];
    vout[t] = acc;
    __syncthreads();
    #pragma unroll
    for (int h = 0; h < 8; h++) {
        float a = 0.f;
        #pragma unroll 8
        for (int d = 0; d < 32; d++)
            a += ipw[(512 + h * 32 + d) * 256 + t] * vout[h * 32 + d];
        g_u[h * 256 + t] = a;
    }
    if (t < 8) {
        float c = 0.f;
        for (int d = 0; d < 32; d++) c += ipb[512 + t * 32 + d] * vout[t * 32 + d];
        g_c[t] = c;
    }
    if (t == 0) {
        float c = 0.f;
        for (int j = 0; j < 256; j++) c += opb[j] * ow[j];
        g_konst[0] = c + ob[0];
    }
}

// ---------------- phase 1: deg ∥ xconv ----------------
// blocks [0, ndeg): degree atomics ; blocks [ndeg, ...): x -> bf16 padded
__global__ void k_front(const int* __restrict__ ei, const float* __restrict__ x,
                        int E, int n, int ndeg) {
    int t = threadIdx.x;
    if ((int)blockIdx.x < ndeg) {
        int i = blockIdx.x * 256 + t;
        if (i < E) atomicAdd(&g_degi[ei[E + i]], 1);
        return;
    }
    int j = (blockIdx.x - ndeg) * 256 + t;
    if (j >= n * 152) return;
    int row = j / 152, p = j % 152;
    uint32_t v = 0;
    if (p < 150) {
        float2 f = *reinterpret_cast<const float2*>(&x[row * FEAT + 2 * p]);
        v = f2_to_bf2(f.x, f.y);
    }
    *reinterpret_cast<uint32_t*>(&g_xb[row * XB_PAD + 2 * p]) = v;
}

// ---------------- phase 2: scanA + dis (fused, same g_degi pass) ------------
__global__ void k_scanA(int n) {
    __shared__ int sh[8];
    int i = blockIdx.x * 256 + threadIdx.x;
    int v = 0;
    if (i < n) {
        v = g_degi[i];
        float d = 1.0f + (float)v;
        g_dis[i]  = rsqrtf(d);
        g_dinv[i] = 1.0f / d;
    }
    int s = v;
    #pragma unroll
    for (int off = 16; off; off >>= 1) s += __shfl_xor_sync(0xffffffffu, s, off);
    if ((threadIdx.x & 31) == 0) sh[threadIdx.x >> 5] = s;
    __syncthreads();
    if (threadIdx.x == 0) {
        int r = 0;
        #pragma unroll
        for (int w = 0; w < 8; w++) r += sh[w];
        g_bsum[blockIdx.x] = r;
    }
}
__global__ void k_scanB(int nb, int n) {
    __shared__ int sh[256];
    int t = threadIdx.x;
    int v = (t < nb) ? g_bsum[t] : 0;
    sh[t] = v;
    __syncthreads();
    #pragma unroll
    for (int off = 1; off < 256; off <<= 1) {
        int u = (t >= off) ? sh[t - off] : 0;
        __syncthreads();
        sh[t] += u;
        __syncthreads();
    }
    if (t < nb) g_bpre[t] = sh[t] - v;
    if (t == nb - 1) g_off[n] = sh[t];
}
__global__ void k_scanC(int n) {
    __shared__ int sh[256];
    int t = threadIdx.x;
    int i = blockIdx.x * 256 + t;
    int v = (i < n) ? g_degi[i] : 0;
    sh[t] = v;
    __syncthreads();
    #pragma unroll
    for (int off = 1; off < 256; off <<= 1) {
        int u = (t >= off) ? sh[t - off] : 0;
        __syncthreads();
        sh[t] += u;
        __syncthreads();
    }
    if (i < n) {
        int off = g_bpre[blockIdx.x] + sh[t] - v;
        g_off[i] = off;
        g_cur[i] = off;
    }
}

// ---------------- phase 3: scatter ∥ wconv2 ∥ wgcn ----------------
// wb2 rows: 0:512 = ipw (Q,K); 512:520 = u_hi = bf16(u); 520:528 = u_lo =
// bf16(u - u_hi) (u is shared by all nodes: its quantization error is a fixed
// bias that does NOT average out in the pool -> two-term split); 528:544 = 0.
__global__ void k_mid(const int* __restrict__ ei, const float* __restrict__ ipw,
                      const float* __restrict__ Ws, const float* __restrict__ Wf,
                      int E, int nsc, int nwc) {
    int t = threadIdx.x;
    int bx = blockIdx.x;
    if (bx < nsc) {
        int i = bx * 256 + t;
        if (i < E) {
            int s = ei[i];
            int d = ei[E + i];
            int pos = atomicAdd(&g_cur[d], 1);
            g_srcs[pos] = s;
        }
        return;
    }
    bx -= nsc;
    if (bx < nwc) {
        int i = bx * 256 + t;   // over 544*128 bf16-pairs
        if (i >= 544 * 128) return;
        int r = i / 128, p = i % 128;
        float a = 0.f, b = 0.f;
        if (r < 512) {
            a = ipw[r * 256 + 2 * p];
            b = ipw[r * 256 + 2 * p + 1];
        } else if (r < 520) {
            a = g_u[(r - 512) * 256 + 2 * p];
            b = g_u[(r - 512) * 256 + 2 * p + 1];
        } else if (r < 528) {
            float ua = g_u[(r - 520) * 256 + 2 * p];
            float ub = g_u[(r - 520) * 256 + 2 * p + 1];
            a = ua - __bfloat162float(__float2bfloat16(ua));
            b = ub - __bfloat162float(__float2bfloat16(ub));
        }
        *reinterpret_cast<uint32_t*>(&g_wb2[r * 256 + 2 * p]) = f2_to_bf2(a, b);
        return;
    }
    bx -= nwc;
    int i = bx * 256 + t;
    if (i >= 512 * 320) return;
    int nn = i / 320, k = i % 320;
    float v = 0.f;
    if (nn < 256) { if (k < 100) v = Ws[k * 256 + nn]; }
    else          { if (k >= 100 && k < 300) v = Wf[(k - 100) * 256 + (nn - 256)]; }
    g_wg[i] = __float2bfloat16(v);
}

// ---------------- phase 4: gather-aggregate + y epilogue ----------------
__global__ __launch_bounds__(256) void k_gather(int n) {
    int w    = (blockIdx.x * blockDim.x + threadIdx.x) >> 5;
    int lane = threadIdx.x & 31;
    if (w >= n) return;
    int beg = g_off[w], end = g_off[w + 1];

    float acc0[8], acc1[8];
    #pragma unroll
    for (int j = 0; j < 8; j++) { acc0[j] = 0.f; acc1[j] = 0.f; }

    for (int base = beg; base < end; base += 32) {
        int cnt = min(32, end - base);
        int   s_l = 0;
        float w_l = 0.f;
        if (lane < cnt) {
            s_l = g_srcs[base + lane];
            w_l = g_dis[s_l];
        }
        for (int k = 0; k < cnt; k++) {
            int   s  = __shfl_sync(0xffffffffu, s_l, k);
            float wt = __shfl_sync(0xffffffffu, w_l, k);
            const uint4* xr = reinterpret_cast<const uint4*>(g_xb + (size_t)s * XB_PAD);
            uint4 v = __ldg(&xr[lane]);
            float2 f;
            f = bf2_to_f2(v.x); acc0[0] += wt * f.x; acc0[1] += wt * f.y;
            f = bf2_to_f2(v.y); acc0[2] += wt * f.x; acc0[3] += wt * f.y;
            f = bf2_to_f2(v.z); acc0[4] += wt * f.x; acc0[5] += wt * f.y;
            f = bf2_to_f2(v.w); acc0[6] += wt * f.x; acc0[7] += wt * f.y;
            if (lane < 6) {
                uint4 v2 = __ldg(&xr[32 + lane]);
                f = bf2_to_f2(v2.x); acc1[0] += wt * f.x; acc1[1] += wt * f.y;
                f = bf2_to_f2(v2.y); acc1[2] += wt * f.x; acc1[3] += wt * f.y;
                f = bf2_to_f2(v2.z); acc1[4] += wt * f.x; acc1[5] += wt * f.y;
                f = bf2_to_f2(v2.w); acc1[6] += wt * f.x; acc1[7] += wt * f.y;
            }
        }
    }

    float dw = g_dis[w], iw = g_dinv[w];
    const uint4* xr = reinterpret_cast<const uint4*>(g_xb + (size_t)w * XB_PAD);
    uint4* yr = reinterpret_cast<uint4*>(g_yb + (size_t)w * XB_PAD);
    {
        uint4 xs = xr[lane];
        float2 f0 = bf2_to_f2(xs.x), f1 = bf2_to_f2(xs.y);
        float2 f2 = bf2_to_f2(xs.z), f3 = bf2_to_f2(xs.w);
        uint4 st;
        st.x = f2_to_bf2(dw * acc0[0] + iw * f0.x, dw * acc0[1] + iw * f0.y);
        st.y = f2_to_bf2(dw * acc0[2] + iw * f1.x, dw * acc0[3] + iw * f1.y);
        st.z = f2_to_bf2(dw * acc0[4] + iw * f2.x, dw * acc0[5] + iw * f2.y);
        st.w = f2_to_bf2(dw * acc0[6] + iw * f3.x, dw * acc0[7] + iw * f3.y);
        yr[lane] = st;
    }
    if (lane < 6) {
        uint4 xs = xr[32 + lane];
        float2 f0 = bf2_to_f2(xs.x), f1 = bf2_to_f2(xs.y);
        float2 f2 = bf2_to_f2(xs.z), f3 = bf2_to_f2(xs.w);
        uint4 st;
        st.x = f2_to_bf2(dw * acc1[0] + iw * f0.x, dw * acc1[1] + iw * f0.y);
        st.y = f2_to_bf2(dw * acc1[2] + iw * f1.x, dw * acc1[3] + iw * f1.y);
        st.z = f2_to_bf2(dw * acc1[4] + iw * f2.x, dw * acc1[5] + iw * f2.y);
        st.w = f2_to_bf2(dw * acc1[6] + iw * f3.x, dw * acc1[7] + iw * f3.y);
        yr[32 + lane] = st;
    }
}

// ---------------- phase 5: GCN GEMM via HMMA (cp.async double-buffered) ------
#define GA_PAD 328
#define GB_ROWB 144                          // 72 bf16 per row
#define G_SM_A   0                           // 64 x 328 x 2 = 41984
#define G_SM_B0  41984
#define G_B_BYTES 73728                      // 512 x 144
#define G_SM_B1  (G_SM_B0 + G_B_BYTES)
#define G_SM_BIAS (G_SM_B1 + G_B_BYTES)      // 189440
#define G_SM_TOTAL (G_SM_BIAS + 2048)

__global__ __launch_bounds__(256, 1) void k_gcn(
        const float* __restrict__ bsg, const float* __restrict__ bfg, int n) {
    extern __shared__ __align__(1024) unsigned char smraw[];
    __nv_bfloat16* A = reinterpret_cast<__nv_bfloat16*>(smraw + G_SM_A);
    float* sbias     = reinterpret_cast<float*>(smraw + G_SM_BIAS);

    int tid = threadIdx.x, wid = tid >> 5, lane = tid & 31;
    int n0 = blockIdx.x * 64;

    uint32_t b0_base = smem_u32(smraw + G_SM_B0);
    uint32_t b1_base = smem_u32(smraw + G_SM_B1);

    #pragma unroll
    for (int it = 0; it < 16; it++) {
        int i = it * 256 + tid;
        int rr = i >> 3, k4 = i & 7;
        cp16(b0_base + rr * GB_ROWB + k4 * 16, &g_wg[rr * 320 + 0 * 64 + k4 * 8]);
    }
    CP_COMMIT();
    #pragma unroll
    for (int it = 0; it < 16; it++) {
        int i = it * 256 + tid;
        int rr = i >> 3, k4 = i & 7;
        cp16(b1_base + rr * GB_ROWB + k4 * 16, &g_wg[rr * 320 + 1 * 64 + k4 * 8]);
    }
    CP_COMMIT();

    sbias[tid]       = bsg[tid];
    sbias[256 + tid] = bfg[tid];

    for (int i = tid; i < 64 * 40; i += 256) {
        int tok = i / 40, k4 = i % 40;
        int node = n0 + tok;
        uint4 v = make_uint4(0u, 0u, 0u, 0u);
        if (node < n && k4 < 38)
            v = *reinterpret_cast<const uint4*>(&g_yb[(size_t)node * XB_PAD + k4 * 8]);
        *reinterpret_cast<uint4*>(&A[tok * GA_PAD + k4 * 8]) = v;
    }

    uint32_t a_base = smem_u32(A);
    int mt = wid & 3;
    int nh = wid >> 2;

    float acc[32][4];
    #pragma unroll
    for (int j = 0; j < 32; j++)
        #pragma unroll
        for (int r = 0; r < 4; r++) acc[j][r] = 0.f;

    int a_row  = mt * 16 + (lane & 15);
    int a_col8 = (lane >> 4) * 8;
    int b_rofs = (lane & 7) + (lane >> 4) * 8;
    int b_col8 = ((lane >> 3) & 1) * 8;

    for (int c = 0; c < 5; c++) {
        if (c < 4) CP_WAIT(1); else CP_WAIT(0);
        __syncthreads();
        uint32_t b_base = (c & 1) ? b1_base : b0_base;

        #pragma unroll
        for (int ks = 0; ks < 4; ks++) {
            uint32_t af[4];
            uint32_t aaddr = a_base +
                (uint32_t)(a_row * GA_PAD + c * 64 + ks * 16 + a_col8) * 2;
            ldsm4(af[0], af[1], af[2], af[3], aaddr);
            #pragma unroll
            for (int j = 0; j < 16; j++) {
                int nrow = nh * 256 + j * 16 + b_rofs;
                uint32_t baddr = b_base + nrow * GB_ROWB + ks * 32 + b_col8 * 2;
                uint32_t b0, b1, b2, b3;
                ldsm4(b0, b1, b2, b3, baddr);
                mma16816(acc[2 * j],     af, b0, b1);
                mma16816(acc[2 * j + 1], af, b2, b3);
            }
        }
        if (c + 2 < 5) {
            __syncthreads();
            uint32_t dstb = (c & 1) ? b1_base : b0_base;
            #pragma unroll
            for (int it = 0; it < 16; it++) {
                int i = it * 256 + tid;
                int rr = i >> 3, k4 = i & 7;
                cp16(dstb + rr * GB_ROWB + k4 * 16,
                     &g_wg[rr * 320 + (c + 2) * 64 + k4 * 8]);
            }
            CP_COMMIT();
        }
    }

    int r0 = mt * 16 + (lane >> 2);
    int node0 = n0 + r0, node1 = node0 + 8;
    int cofs = (lane & 3) * 2;
    #pragma unroll
    for (int j = 0; j < 32; j++) {
        int col = nh * 256 + j * 8 + cofs;
        float b0 = sbias[col], b1 = sbias[col + 1];
        if (node0 < n) {
            uint32_t p = f2_to_bf2(fmaxf(acc[j][0] + b0, 0.f),
                                   fmaxf(acc[j][1] + b1, 0.f));
            *reinterpret_cast<uint32_t*>(&g_sfb[(size_t)node0 * 512 + col]) = p;
        }
        if (node1 < n) {
            uint32_t p = f2_to_bf2(fmaxf(acc[j][2] + b0, 0.f),
                                   fmaxf(acc[j][3] + b1, 0.f));
            *reinterpret_cast<uint32_t*>(&g_sfb[(size_t)node1 * 512 + col]) = p;
        }
    }
}

// ---------------- phase 6: HMMA QK+dv projection + attention -----------------
// 32 nodes = 64 tok/block. B = 544 rows (Q 0:256, K 256:512, u_hi 512:520,
// u_lo 520:528, pad). Out fp32 [64][552] unioned over B double-buffers.
#define AT_PAD 264
#define AB_ROWB 144
#define OUT_PAD 552
#define A_SM_A   0                            // 64 x 264 x 2 = 33792
#define A_SM_B0  33792
#define A_B_BYTES 78336                       // 544 x 144
#define A_SM_B1  (A_SM_B0 + A_B_BYTES)        // 112128
#define A_SM_BIAS 190464                      // 544 x 4 = 2176
#define A_SM_RED  (A_SM_BIAS + 2176)
#define A_SM_TOTAL (A_SM_RED + 64)

__global__ __launch_bounds__(256, 1) void k_attn(
        const float* __restrict__ ipb, int n) {
    extern __shared__ __align__(1024) unsigned char smraw[];
    __nv_bfloat16* A = reinterpret_cast<__nv_bfloat16*>(smraw + A_SM_A);
    float* Out   = reinterpret_cast<float*>(smraw + A_SM_B0);
    float* sbias = reinterpret_cast<float*>(smraw + A_SM_BIAS);
    float* red   = reinterpret_cast<float*>(smraw + A_SM_RED);

    int tid = threadIdx.x, wid = tid >> 5, lane = tid & 31;
    int n0 = blockIdx.x * 32;

    uint32_t b0_base = smem_u32(smraw + A_SM_B0);
    uint32_t b1_base = smem_u32(smraw + A_SM_B1);

    #pragma unroll
    for (int it = 0; it < 17; it++) {
        int i = it * 256 + tid;
        int rr = i >> 3, k4 = i & 7;
        cp16(b0_base + rr * AB_ROWB + k4 * 16, &g_wb2[rr * 256 + 0 * 64 + k4 * 8]);
    }
    CP_COMMIT();
    #pragma unroll
    for (int it = 0; it < 17; it++) {
        int i = it * 256 + tid;
        int rr = i >> 3, k4 = i & 7;
        cp16(b1_base + rr * AB_ROWB + k4 * 16, &g_wb2[rr * 256 + 1 * 64 + k4 * 8]);
    }
    CP_COMMIT();

    // bias: 0:512 = ipb, 512:520 = g_c, rest 0 (u_lo rows get no bias)
    for (int i = tid; i < 544; i += 256) {
        float v = 0.f;
        if (i < 512) v = ipb[i];
        else if (i < 520) v = g_c[i - 512];
        sbias[i] = v;
    }

    #pragma unroll
    for (int it = 0; it < 16; it++) {
        int i = it * 256 + tid;
        int tok = i >> 6, k4 = i & 63;
        int node = n0 + (tok >> 1);
        unsigned long long v = 0ull;
        if (node < n)
            v = *reinterpret_cast<const unsigned long long*>(
                    &g_sfb[(size_t)node * 512 + (tok & 1) * 256 + k4 * 4]);
        *reinterpret_cast<unsigned long long*>(&A[tok * AT_PAD + k4 * 4]) = v;
    }

    uint32_t a_base = smem_u32(A);
    int mt = wid & 3;
    int nh = wid >> 2;

    float acc[34][4];
    #pragma unroll
    for (int j = 0; j < 34; j++)
        #pragma unroll
        for (int r = 0; r < 4; r++) acc[j][r] = 0.f;

    int a_row = mt * 16 + (lane & 15);
    int a_col8 = (lane >> 4) * 8;
    int b_rofs = (lane & 7) + (lane >> 4) * 8;
    int b_col8 = ((lane >> 3) & 1) * 8;

    for (int c = 0; c < 4; c++) {
        if (c < 3) CP_WAIT(1); else CP_WAIT(0);
        __syncthreads();
        uint32_t b_base = (c & 1) ? b1_base : b0_base;

        #pragma unroll
        for (int ks = 0; ks < 4; ks++) {
            uint32_t af[4];
            uint32_t aaddr = a_base +
                (uint32_t)(a_row * AT_PAD + c * 64 + ks * 16 + a_col8) * 2;
            ldsm4(af[0], af[1], af[2], af[3], aaddr);
            #pragma unroll
            for (int j = 0; j < 17; j++) {
                int nrow = nh * 272 + j * 16 + b_rofs;
                uint32_t baddr = b_base + nrow * AB_ROWB + ks * 32 + b_col8 * 2;
                uint32_t b0, b1, b2, b3;
                ldsm4(b0, b1, b2, b3, baddr);
                mma16816(acc[2 * j],     af, b0, b1);
                mma16816(acc[2 * j + 1], af, b2, b3);
            }
        }
        if (c + 2 < 4) {
            __syncthreads();
            uint32_t dstb = (c & 1) ? b1_base : b0_base;
            #pragma unroll
            for (int it = 0; it < 17; it++) {
                int i = it * 256 + tid;
                int rr = i >> 3, k4 = i & 7;
                cp16(dstb + rr * AB_ROWB + k4 * 16,
                     &g_wb2[rr * 256 + (c + 2) * 64 + k4 * 8]);
            }
            CP_COMMIT();
        }
    }
    __syncthreads();   // all MMA reads done -> Out may overwrite B region

    {
        int row0 = mt * 16 + (lane >> 2);
        int cofs = (lane & 3) * 2;
        #pragma unroll
        for (int j = 0; j < 34; j++) {
            int col = nh * 272 + j * 8 + cofs;
            float bb0 = sbias[col], bb1 = sbias[col + 1];
            Out[row0 * OUT_PAD + col]           = acc[j][0] + bb0;
            Out[row0 * OUT_PAD + col + 1]       = acc[j][1] + bb1;
            Out[(row0 + 8) * OUT_PAD + col]     = acc[j][2] + bb0;
            Out[(row0 + 8) * OUT_PAD + col + 1] = acc[j][3] + bb1;
        }
    }
    __syncthreads();

    // per (node, head) 2x2 attention; dv = u_hi col + u_lo col
    int node = tid >> 3, h = tid & 7;
    const float4* q0 = reinterpret_cast<const float4*>(
        &Out[(node * 2 + 0) * OUT_PAD + h * 32]);
    const float4* q1 = reinterpret_cast<const float4*>(
        &Out[(node * 2 + 1) * OUT_PAD + h * 32]);
    const float4* k0 = reinterpret_cast<const float4*>(
        &Out[(node * 2 + 0) * OUT_PAD + 256 + h * 32]);
    const float4* k1 = reinterpret_cast<const float4*>(
        &Out[(node * 2 + 1) * OUT_PAD + 256 + h * 32]);
    float s00 = 0.f, s01 = 0.f, s10 = 0.f, s11 = 0.f;
    #pragma unroll
    for (int d = 0; d < 8; d++) {
        float4 a0 = q0[d], a1 = q1[d], b0 = k0[d], b1 = k1[d];
        s00 += a0.x * b0.x + a0.y * b0.y + a0.z * b0.z + a0.w * b0.w;
        s01 += a0.x * b1.x + a0.y * b1.y + a0.z * b1.z + a0.w * b1.w;
        s10 += a1.x * b0.x + a1.y * b0.y + a1.z * b0.z + a1.w * b0.w;
        s11 += a1.x * b1.x + a1.y * b1.y + a1.z * b1.z + a1.w * b1.w;
    }
    const float scale = 0.17677669529663687f;
    s00 *= scale; s01 *= scale; s10 *= scale; s11 *= scale;
    float m0 = fmaxf(s00, s01), m1 = fmaxf(s10, s11);
    float e00 = expf(s00 - m0), e01 = expf(s01 - m0);
    float e10 = expf(s10 - m1), e11 = expf(s11 - m1);
    float d0 = e00 + e01, d1 = e10 + e11;
    float a00 = e00 / d0, a01 = e01 / d0;
    float a10 = e10 / d1, a11 = e11 / d1;
    float dv0 = Out[(node * 2 + 0) * OUT_PAD + 512 + h]
              + Out[(node * 2 + 0) * OUT_PAD + 520 + h];
    float dv1 = Out[(node * 2 + 1) * OUT_PAD + 512 + h]
              + Out[(node * 2 + 1) * OUT_PAD + 520 + h];
    float contrib = 0.5f * ((a00 + a10) * dv0 + (a01 + a11) * dv1);
    if (n0 + node >= n) contrib = 0.f;

    #pragma unroll
    for (int off = 16; off; off >>= 1)
        contrib += __shfl_xor_sync(0xffffffffu, contrib, off);
    if (lane == 0) red[wid] = contrib;
    __syncthreads();
    if (tid == 0) {
        float s = 0.f;
        #pragma unroll
        for (int w = 0; w < 8; w++) s += red[w];
        atomicAdd(&g_acc[0], s);
    }
}

// ---------------- phase 7: final scalar ----------------
__global__ void k_final(float* __restrict__ out, int n) {
    out[0] = g_acc[0] / (float)n + g_konst[0];
}

// ---------------- launch ----------------
extern "C" void kernel_launch(void* const* d_in, const int* in_sizes, int n_in,
                              void* d_out, int out_size) {
    const float* x   = (const float*)d_in[0];
    const int*   ei  = (const int*)d_in[1];
    const float* W_s = (const float*)d_in[2];
    const float* b_s = (const float*)d_in[3];
    const float* W_f = (const float*)d_in[4];
    const float* b_f = (const float*)d_in[5];
    const float* ipw = (const float*)d_in[6];
    const float* ipb = (const float*)d_in[7];
    const float* opw = (const float*)d_in[8];
    const float* opb = (const float*)d_in[9];
    const float* ow  = (const float*)d_in[10];
    const float* ob  = (const float*)d_in[11];

    int n = in_sizes[0] / FEAT;
    int E = in_sizes[1] / 2;
    int nb  = (n + 255) / 256;             // scan blocks
    int ndeg = (E + 255) / 256;            // degree/scatter blocks
    int nxc  = (n * 152 + 255) / 256;      // xconv blocks
    int nwc  = (544 * 128 + 255) / 256;    // wconv2 blocks
    int nwg  = (512 * 320 + 255) / 256;    // wgcn blocks

    k_init <<<nb + 1, 256>>>(ipw, ipb, opw, opb, ow, ob, n, nb);
    k_front<<<ndeg + nxc, 256>>>(ei, x, E, n, ndeg);
    k_scanA<<<nb, 256>>>(n);
    k_scanB<<<1, 256>>>(nb, n);
    k_scanC<<<nb, 256>>>(n);
    k_mid  <<<ndeg + nwc + nwg, 256>>>(ei, ipw, W_s, W_f, E, ndeg, nwc);
    k_gather<<<(n + 7) / 8, 256>>>(n);

    cudaFuncSetAttribute(k_gcn, cudaFuncAttributeMaxDynamicSharedMemorySize, G_SM_TOTAL);
    k_gcn<<<(n + 63) / 64, 256, G_SM_TOTAL>>>(b_s, b_f, n);

    cudaFuncSetAttribute(k_attn, cudaFuncAttributeMaxDynamicSharedMemorySize, A_SM_TOTAL);
    k_attn<<<(n + 31) / 32, 256, A_SM_TOTAL>>>(ipb, n);

    k_final<<<1, 1>>>((float*)d_out, n);
}